// round 9
// baseline (speedup 1.0000x reference)
#include <cuda_runtime.h>
#include <cuda_bf16.h>
#include <math.h>

// Problem constants
constexpr int B_ = 8, N_ = 2048;
constexpr int M1 = 1024, M2 = 512;
constexpr int H1 = 128, C1OUT = 128;
constexpr int H2 = 256, C2OUT = 512;
constexpr int KMAX = 64;
constexpr int QPB = 32;   // queries per conv block (2 per warp)
constexpr int MT  = 64;   // pair m-tile
constexpr int NT  = 128;  // n-tile
constexpr int KT  = 32;   // k-tile

// ---------------- scratch (__device__ globals; no allocation allowed) ----------------
// NOTE: referenced ONLY inside device code (host-side use passes host shadow!).
__device__ float g_p   [B_*N_*3];
__device__ int   g_idx1[B_*M1];
__device__ float g_pos1[B_*M1*3];
__device__ float g_P1  [B_*M1*H1];
__device__ float g_Q1  [B_*M1*H1];
__device__ float g_x1  [B_*M1*C1OUT];
__device__ int   g_idx2[B_*M2];
__device__ float g_pos2[B_*M2*3];
__device__ float g_P2  [B_*M2*H2];
__device__ float g_Q2  [B_*M2*H2];

// ---------------- normalize: per-cloud mean / unbiased std ----------------
// Sequential per-coordinate accumulation (verified passing; do not perturb).
__global__ void k_normalize(const float* __restrict__ pos) {
    int b = blockIdx.x, tid = threadIdx.x;           // 512 threads
    __shared__ float s_mean[3], s_den[3];
    const float* p = pos + b*N_*3;

    if (tid < 3) {
        float s = 0.f;
        for (int i = 0; i < N_; ++i) s = __fadd_rn(s, p[i*3 + tid]);
        s_mean[tid] = __fdiv_rn(s, (float)N_);
    }
    __syncthreads();
    if (tid < 3) {
        float mu = s_mean[tid];
        float s = 0.f;
        for (int i = 0; i < N_; ++i) {
            float d = __fsub_rn(p[i*3 + tid], mu);
            s = __fadd_rn(s, __fmul_rn(d, d));
        }
        float var = __fdiv_rn(s, (float)(N_ - 1));
        s_den[tid] = __fadd_rn(__fsqrt_rn(var), 1e-6f);
    }
    __syncthreads();
    float mx = s_mean[0], my = s_mean[1], mz = s_mean[2];
    float dx0 = s_den[0], dy0 = s_den[1], dz0 = s_den[2];
    for (int i = tid; i < N_; i += 512) {
        g_p[(b*N_+i)*3+0] = __fdiv_rn(__fsub_rn(p[i*3+0], mx), dx0);
        g_p[(b*N_+i)*3+1] = __fdiv_rn(__fsub_rn(p[i*3+1], my), dy0);
        g_p[(b*N_+i)*3+2] = __fdiv_rn(__fsub_rn(p[i*3+2], mz), dz0);
    }
}

// ---------------- farthest point sampling ----------------
// Single barrier per iteration; global winner resolved by one 64-bit smem
// atomicMax with key = (dist_bits << 32) | (0x7fffffff - index):
//   max over keys == max distance, ties -> min index (exact jnp.argmax semantics).
// Key slots triple-buffered by iteration so resets never race with readers.
template<int NP, int KSEL, int PT, int LVL>
__global__ void __launch_bounds__(512)
k_fps() {
    constexpr int T = NP / PT;    // 512 threads
    const float* src   = (LVL == 1) ? g_p    : g_pos1;
    int*       idx_out = (LVL == 1) ? g_idx1 : g_idx2;
    float*     pos_out = (LVL == 1) ? g_pos1 : g_pos2;

    int b = blockIdx.x, t = threadIdx.x;
    __shared__ float sx[NP], sy[NP], sz[NP];
    __shared__ unsigned long long s_key[3];
    __shared__ int s_hist[KSEL];
    const float* p = src + b*NP*3;

    float px[PT], py[PT], pz[PT], dd[PT];
    #pragma unroll
    for (int s=0;s<PT;s++){
        int i = t + s*T;
        float x=p[i*3+0], y=p[i*3+1], z=p[i*3+2];
        px[s]=x; py[s]=y; pz[s]=z; dd[s]=1e10f;
        sx[i]=x; sy[i]=y; sz[i]=z;
    }
    if (t < 3) s_key[t] = 0ull;
    if (t == 0) s_hist[0] = 0;
    __syncthreads();

    int win = 0;
    for (int it=1; it<KSEL; ++it) {
        float lx=sx[win], ly=sy[win], lz=sz[win];     // broadcast LDS
        float bd = -1.f; int bi = 0;
        #pragma unroll
        for (int s=0;s<PT;s++){
            float dx=__fsub_rn(px[s],lx), dy=__fsub_rn(py[s],ly), dz=__fsub_rn(pz[s],lz);
            float d = __fadd_rn(__fadd_rn(__fmul_rn(dx,dx),__fmul_rn(dy,dy)),__fmul_rn(dz,dz));
            dd[s] = fminf(dd[s], d);
            if (dd[s] > bd) { bd = dd[s]; bi = t + s*T; }  // strict >: lowest index per thread
        }
        unsigned mybits = __float_as_uint(bd);              // dist >= 0 -> monotone bits
        unsigned mb = __reduce_max_sync(0xffffffffu, mybits);
        int slot = it % 3;
        if (mybits == mb) {                                 // usually one lane per warp
            unsigned long long key = ((unsigned long long)mb << 32)
                                   | (unsigned)(0x7fffffff - bi);
            atomicMax(&s_key[slot], key);
        }
        if (t == 0) s_key[(it+1) % 3] = 0ull;               // reset future slot (race-free)
        __syncthreads();                                    // ONLY barrier per iteration
        unsigned long long k = s_key[slot];
        win = 0x7fffffff - (int)(unsigned)(k & 0xffffffffu);
        if (t == 0) s_hist[it] = win;
    }
    __syncthreads();
    // bulk write-out, off the serial critical path
    for (int i = t; i < KSEL; i += T) {
        int h = s_hist[i];
        idx_out[b*KSEL+i] = h;
        pos_out[(b*KSEL+i)*3+0] = sx[h];
        pos_out[(b*KSEL+i)*3+1] = sy[h];
        pos_out[(b*KSEL+i)*3+2] = sz[h];
    }
}

// ---------------- level-1 P/Q precompute (BN folded) ----------------
__global__ void k_prep1(const float* __restrict__ w1, const float* __restrict__ b1,
                        const float* __restrict__ g, const float* __restrict__ beta,
                        const float* __restrict__ m, const float* __restrict__ v) {
    int idx = blockIdx.x*256 + threadIdx.x;
    if (idx >= B_*M1*H1) return;
    int c = idx & (H1-1), pj = idx >> 7;
    float x = g_pos1[pj*3+0], y = g_pos1[pj*3+1], z = g_pos1[pj*3+2];
    float s = g[c] / sqrtf(v[c] + 1e-5f);
    float t = beta[c] - m[c]*s;
    float wa0=w1[0*H1+c], wa1=w1[1*H1+c], wa2=w1[2*H1+c];
    float wb0=w1[3*H1+c], wb1=w1[4*H1+c], wb2=w1[5*H1+c];
    float A = x*(wa0+wb0) + y*(wa1+wb1) + z*(wa2+wb2) + b1[c];
    g_P1[idx] = A * s;
    float q = -(x*wb0 + y*wb1 + z*wb2);
    g_Q1[idx] = q * s + t;
}

// ---------------- level-2 P precompute: gathered GEMM [4096,128]@[128,256] ----------------
__global__ void k_prep2(const float* __restrict__ w1, const float* __restrict__ b1,
                        const float* __restrict__ g, const float* __restrict__ v) {
    extern __shared__ char smemraw[];
    float* xs = (float*)smemraw;            // [64][128]
    float* ws = xs + 64*128;                // [128][68] padded
    int tid = threadIdx.x;                  // 256
    int row0 = blockIdx.x * 64;             // global row in [0,4096)
    int n0   = blockIdx.y * 64;
    int b = row0 / M2;

    for (int i = tid; i < 64*128; i += 256) {
        int r = i >> 7, k = i & 127;
        int jj = g_idx2[row0 + r];
        xs[r*128 + k] = g_x1[(b*M1 + jj)*H1 + k];
    }
    for (int i = tid; i < 128*64; i += 256) {
        int k = i >> 6, nn = i & 63;
        ws[k*68 + nn] = w1[k*H2 + n0 + nn];
    }
    __syncthreads();

    int ty = tid >> 4, tx = tid & 15;
    float acc[4][4] = {};
    #pragma unroll 4
    for (int k = 0; k < 128; ++k) {
        float a0 = xs[(ty*4+0)*128 + k];
        float a1 = xs[(ty*4+1)*128 + k];
        float a2 = xs[(ty*4+2)*128 + k];
        float a3 = xs[(ty*4+3)*128 + k];
        float4 bv = *(const float4*)&ws[k*68 + tx*4];
        acc[0][0]+=a0*bv.x; acc[0][1]+=a0*bv.y; acc[0][2]+=a0*bv.z; acc[0][3]+=a0*bv.w;
        acc[1][0]+=a1*bv.x; acc[1][1]+=a1*bv.y; acc[1][2]+=a1*bv.z; acc[1][3]+=a1*bv.w;
        acc[2][0]+=a2*bv.x; acc[2][1]+=a2*bv.y; acc[2][2]+=a2*bv.z; acc[2][3]+=a2*bv.w;
        acc[3][0]+=a3*bv.x; acc[3][1]+=a3*bv.y; acc[3][2]+=a3*bv.z; acc[3][3]+=a3*bv.w;
    }
    #pragma unroll
    for (int mi=0; mi<4; ++mi) {
        int r = row0 + ty*4 + mi;
        float px = g_pos2[r*3+0], py = g_pos2[r*3+1], pz = g_pos2[r*3+2];
        #pragma unroll
        for (int ni=0; ni<4; ++ni) {
            int n = n0 + tx*4 + ni;
            float s = g[n] / sqrtf(v[n] + 1e-5f);
            float A = acc[mi][ni]
                    + px*w1[128*H2 + n] + py*w1[129*H2 + n] + pz*w1[130*H2 + n] + b1[n];
            g_P2[r*H2 + n] = A * s;
        }
    }
}

__global__ void k_prep2q(const float* __restrict__ w1, const float* __restrict__ g,
                         const float* __restrict__ beta, const float* __restrict__ m,
                         const float* __restrict__ v) {
    int idx = blockIdx.x*256 + threadIdx.x;
    if (idx >= B_*M2*H2) return;
    int c = idx & (H2-1), pj = idx >> 8;
    float x = g_pos2[pj*3+0], y = g_pos2[pj*3+1], z = g_pos2[pj*3+2];
    float s = g[c] / sqrtf(v[c] + 1e-5f);
    float t = beta[c] - m[c]*s;
    float q = -(x*w1[128*H2+c] + y*w1[129*H2+c] + z*w1[130*H2+c]);
    g_Q2[idx] = q * s + t;
}

// ---------------- ball-query + pair-list GEMM + max aggregation ----------------
constexpr size_t conv_smem_bytes(int MSRC, int HDIM, int COUT) {
    return (size_t)(MSRC*3 + QPB*KMAX + QPB*KMAX + QPB + QPB*KMAX + QPB*KMAX + 64
                    + MT*HDIM + KT*(NT+4) + QPB*COUT) * 4;
}

template<int MSRC, int HDIM, int COUT, int LVL>
__global__ void __launch_bounds__(512)
k_conv(const float* __restrict__ w2, const float* __restrict__ b2,
       float* __restrict__ out_ext, float R2) {
    const float* srcpos = (LVL == 1) ? g_pos1 : g_pos2;
    const float* P      = (LVL == 1) ? g_P1   : g_P2;
    const float* Q      = (LVL == 1) ? g_Q1   : g_Q2;
    float*       out    = (LVL == 1) ? g_x1   : out_ext;

    extern __shared__ char smemraw[];
    float*    s_pos = (float*)smemraw;                 // MSRC*3
    float*    s_pd  = s_pos + MSRC*3;                  // QPB*KMAX
    int*      s_pj  = (int*)(s_pd + QPB*KMAX);         // QPB*KMAX
    int*      s_cnt = s_pj + QPB*KMAX;                 // QPB
    int*      s_fi  = s_cnt + QPB;                     // QPB*KMAX
    int*      s_fj  = s_fi + QPB*KMAX;                 // QPB*KMAX
    int*      s_qoff= s_fj + QPB*KMAX;                 // 64
    float*    s_h   = (float*)(s_qoff + 64);           // MT*HDIM
    float*    s_w   = s_h + MT*HDIM;                   // KT*(NT+4)
    unsigned* s_out = (unsigned*)(s_w + KT*(NT+4));    // QPB*COUT

    int blk = blockIdx.x;
    int b  = blk / (MSRC/QPB);
    int q0 = (blk % (MSRC/QPB)) * QPB;
    int tid = threadIdx.x, lane = tid & 31, w = tid >> 5;

    for (int i = tid; i < MSRC*3; i += 512) s_pos[i] = srcpos[b*MSRC*3 + i];
    __syncthreads();

    // ---- pair build: warp w handles queries q0+2w, q0+2w+1 ----
    for (int qq = 0; qq < 2; ++qq) {
        int qslot = w*2 + qq;
        int qi = q0 + qslot;
        float qx = s_pos[qi*3+0], qy = s_pos[qi*3+1], qz = s_pos[qi*3+2];
        int cnt = 0;
        for (int base = 0; base < MSRC; base += 32) {
            int j = base + lane;
            float dx = __fsub_rn(s_pos[j*3+0], qx);
            float dy = __fsub_rn(s_pos[j*3+1], qy);
            float dz = __fsub_rn(s_pos[j*3+2], qz);
            float d2 = __fadd_rn(__fadd_rn(__fmul_rn(dx,dx),__fmul_rn(dy,dy)),__fmul_rn(dz,dz));
            bool pred = (d2 <= R2);
            unsigned ball = __ballot_sync(0xffffffffu, pred);
            int nb = __popc(ball);
            if (cnt + nb <= KMAX) {
                if (pred) {
                    int pos = cnt + __popc(ball & ((1u<<lane)-1u));
                    s_pj[qslot*KMAX+pos] = j; s_pd[qslot*KMAX+pos] = d2;
                }
                cnt += nb;
            } else {
                // rare slow path: keep K smallest d2 (ties -> lower j kept)
                unsigned rem = ball;
                while (rem) {
                    int l = __ffs(rem)-1; rem &= rem-1u;
                    float cd2 = __shfl_sync(0xffffffffu, d2, l);
                    int cj = base + l;
                    if (cnt < KMAX) {
                        if (lane==0){ s_pj[qslot*KMAX+cnt]=cj; s_pd[qslot*KMAX+cnt]=cd2; }
                        cnt++;
                    } else {
                        float e0 = s_pd[qslot*KMAX+lane],    e1 = s_pd[qslot*KMAX+32+lane];
                        int   j0 = s_pj[qslot*KMAX+lane],    j1 = s_pj[qslot*KMAX+32+lane];
                        float md; int ms, mj;
                        if (e1 > e0 || (e1==e0 && j1>j0)) { md=e1; ms=32+lane; mj=j1; }
                        else                               { md=e0; ms=lane;    mj=j0; }
                        #pragma unroll
                        for (int o=16;o;o>>=1){
                            float od = __shfl_xor_sync(~0u, md, o);
                            int   os = __shfl_xor_sync(~0u, ms, o);
                            int   oj = __shfl_xor_sync(~0u, mj, o);
                            if (od > md || (od==md && oj>mj)) { md=od; ms=os; mj=oj; }
                        }
                        if (cd2 < md) {
                            if (lane==0){ s_pj[qslot*KMAX+ms]=cj; s_pd[qslot*KMAX+ms]=cd2; }
                        }
                    }
                    __syncwarp();
                }
            }
        }
        if (lane==0) s_cnt[qslot] = cnt;
    }
    __syncthreads();

    if (tid==0){
        int acc=0;
        for (int i=0;i<QPB;i++){ s_qoff[i]=acc; acc+=s_cnt[i]; }
        s_qoff[QPB]=acc;
    }
    __syncthreads();
    for (int qq = 0; qq < 2; ++qq) {
        int qslot = w*2 + qq;
        int off = s_qoff[qslot], c = s_cnt[qslot];
        for (int e = lane; e < c; e += 32){ s_fi[off+e]=qslot; s_fj[off+e]=s_pj[qslot*KMAX+e]; }
    }
    for (int i = tid; i < QPB*COUT; i += 512) s_out[i] = 0u;
    __syncthreads();

    int total = s_qoff[QPB];
    int ty = tid >> 5, tx = tid & 31;

    for (int m0 = 0; m0 < total; m0 += MT) {
        // hidden tile: h = relu(P_j + Q_i)
        for (int i = tid; i < MT*HDIM; i += 512) {
            int mp = i / HDIM, k = i % HDIM;
            float val = 0.f;
            if (m0 + mp < total) {
                int qi = s_fi[m0+mp], j = s_fj[m0+mp];
                val = fmaxf(P[(size_t)(b*MSRC + j)*HDIM + k] + Q[(size_t)(b*MSRC + q0 + qi)*HDIM + k], 0.f);
            }
            s_h[i] = val;
        }
        __syncthreads();

        for (int n0 = 0; n0 < COUT; n0 += NT) {
            float acc[4][4] = {};
            for (int k0 = 0; k0 < HDIM; k0 += KT) {
                for (int i = tid; i < KT*NT; i += 512) {
                    int kk = i / NT, nn = i % NT;
                    s_w[kk*(NT+4)+nn] = w2[(size_t)(k0+kk)*COUT + n0 + nn];
                }
                __syncthreads();
                #pragma unroll
                for (int kk = 0; kk < KT; ++kk) {
                    float a0 = s_h[(ty*4+0)*HDIM + k0+kk];
                    float a1 = s_h[(ty*4+1)*HDIM + k0+kk];
                    float a2 = s_h[(ty*4+2)*HDIM + k0+kk];
                    float a3 = s_h[(ty*4+3)*HDIM + k0+kk];
                    float4 bv = *(const float4*)&s_w[kk*(NT+4) + tx*4];
                    acc[0][0]+=a0*bv.x; acc[0][1]+=a0*bv.y; acc[0][2]+=a0*bv.z; acc[0][3]+=a0*bv.w;
                    acc[1][0]+=a1*bv.x; acc[1][1]+=a1*bv.y; acc[1][2]+=a1*bv.z; acc[1][3]+=a1*bv.w;
                    acc[2][0]+=a2*bv.x; acc[2][1]+=a2*bv.y; acc[2][2]+=a2*bv.z; acc[2][3]+=a2*bv.w;
                    acc[3][0]+=a3*bv.x; acc[3][1]+=a3*bv.y; acc[3][2]+=a3*bv.z; acc[3][3]+=a3*bv.w;
                }
                __syncthreads();
            }
            #pragma unroll
            for (int mi=0; mi<4; ++mi) {
                int mp = ty*4 + mi;
                if (m0 + mp < total) {
                    int qi = s_fi[m0+mp];
                    #pragma unroll
                    for (int ni=0; ni<4; ++ni) {
                        int n = n0 + tx*4 + ni;
                        float val = fmaxf(acc[mi][ni] + b2[n], 0.f);
                        atomicMax(&s_out[qi*COUT + n], __float_as_uint(val));
                    }
                }
            }
            __syncthreads();
        }
    }

    for (int i = tid; i < QPB*COUT; i += 512) {
        int q = i / COUT, c = i % COUT;
        out[(size_t)(b*MSRC + q0 + q)*COUT + c] = __uint_as_float(s_out[i]);
    }
}

// batch2: second output written as float32 into the shared float output buffer.
__global__ void k_batch2(float* __restrict__ out) {
    int i = blockIdx.x*256 + threadIdx.x;
    if (i < B_*M2) out[i] = (float)(i >> 9);   // batch id 0..7
}

// ---------------- launch ----------------
extern "C" void kernel_launch(void* const* d_in, const int* in_sizes, int n_in,
                              void* d_out, int out_size) {
    const float *pos, *c1_w1, *c1_b1, *c1_g, *c1_be, *c1_m, *c1_v, *c1_w2, *c1_b2;
    const float *c2_w1, *c2_b1, *c2_g, *c2_be, *c2_m, *c2_v, *c2_w2, *c2_b2;
    if (in_sizes[0] == B_*N_*3) {
        // setup_inputs insertion order
        pos   = (const float*)d_in[0];
        c1_w1 = (const float*)d_in[1];  c1_b1 = (const float*)d_in[2];
        c1_g  = (const float*)d_in[3];  c1_be = (const float*)d_in[4];
        c1_m  = (const float*)d_in[5];  c1_v  = (const float*)d_in[6];
        c1_w2 = (const float*)d_in[7];  c1_b2 = (const float*)d_in[8];
        c2_w1 = (const float*)d_in[9];  c2_b1 = (const float*)d_in[10];
        c2_g  = (const float*)d_in[11]; c2_be = (const float*)d_in[12];
        c2_m  = (const float*)d_in[13]; c2_v  = (const float*)d_in[14];
        c2_w2 = (const float*)d_in[15]; c2_b2 = (const float*)d_in[16];
    } else {
        // alphabetical fallback
        c1_b1 = (const float*)d_in[1];  c1_b2 = (const float*)d_in[2];
        c1_be = (const float*)d_in[3];  c1_g  = (const float*)d_in[4];
        c1_m  = (const float*)d_in[5];  c1_v  = (const float*)d_in[6];
        c1_w1 = (const float*)d_in[7];  c1_w2 = (const float*)d_in[8];
        c2_b1 = (const float*)d_in[9];  c2_b2 = (const float*)d_in[10];
        c2_be = (const float*)d_in[11]; c2_g  = (const float*)d_in[12];
        c2_m  = (const float*)d_in[13]; c2_v  = (const float*)d_in[14];
        c2_w1 = (const float*)d_in[15]; c2_w2 = (const float*)d_in[16];
        pos   = (const float*)d_in[17];
    }
    float* out = (float*)d_out;

    const size_t smem1 = conv_smem_bytes(M1, H1, C1OUT);
    const size_t smem2 = conv_smem_bytes(M2, H2, C2OUT);
    const size_t smemP2 = (64*128 + 128*68) * sizeof(float);
    cudaFuncSetAttribute(k_conv<M1,H1,C1OUT,1>, cudaFuncAttributeMaxDynamicSharedMemorySize, (int)smem1);
    cudaFuncSetAttribute(k_conv<M2,H2,C2OUT,2>, cudaFuncAttributeMaxDynamicSharedMemorySize, (int)smem2);
    cudaFuncSetAttribute(k_prep2, cudaFuncAttributeMaxDynamicSharedMemorySize, (int)smemP2);

    // Fork a side stream so fps2 overlaps prep1+conv1 (both depend only on fps1).
    cudaStream_t s2;
    cudaStreamCreateWithFlags(&s2, cudaStreamNonBlocking);
    cudaEvent_t e1, e2;
    cudaEventCreateWithFlags(&e1, cudaEventDisableTiming);
    cudaEventCreateWithFlags(&e2, cudaEventDisableTiming);

    k_normalize<<<B_, 512>>>(pos);
    k_fps<N_, M1, 4, 1><<<B_, 512>>>();

    cudaEventRecord(e1, 0);
    cudaStreamWaitEvent(s2, e1, 0);
    // side stream: batch2 (independent) + fps2 (needs only g_pos1)
    if ((size_t)out_size >= (size_t)B_*M2*C2OUT + B_*M2) {
        k_batch2<<<(B_*M2 + 255)/256, 256, 0, s2>>>(out + (size_t)B_*M2*C2OUT);
    }
    k_fps<M1, M2, 2, 2><<<B_, 512, 0, s2>>>();

    // main stream: level-1 conv pipeline
    k_prep1<<<(B_*M1*H1 + 255)/256, 256>>>(c1_w1, c1_b1, c1_g, c1_be, c1_m, c1_v);
    {
        float r2 = (float)(0.1 * 0.1);   // matches JAX f32 scalar exactly
        k_conv<M1,H1,C1OUT,1><<<B_*(M1/QPB), 512, smem1>>>(c1_w2, c1_b2, nullptr, r2);
    }

    cudaEventRecord(e2, s2);
    cudaStreamWaitEvent(0, e2, 0);

    k_prep2<<<dim3(B_*M2/64, H2/64), 256, smemP2>>>(c2_w1, c2_b1, c2_g, c2_v);
    k_prep2q<<<(B_*M2*H2 + 255)/256, 256>>>(c2_w1, c2_g, c2_be, c2_m, c2_v);
    {
        float r2 = (float)(0.25 * 0.25);
        k_conv<M2,H2,C2OUT,2><<<B_*(M2/QPB), 512, smem2>>>(c2_w2, c2_b2, out, r2);
    }

    cudaEventDestroy(e1);
    cudaEventDestroy(e2);
    cudaStreamDestroy(s2);
    (void)in_sizes; (void)n_in;
}

// round 10
// speedup vs baseline: 1.4707x; 1.4707x over previous
#include <cuda_runtime.h>
#include <cuda_bf16.h>
#include <math.h>

// Problem constants
constexpr int B_ = 8, N_ = 2048;
constexpr int M1 = 1024, M2 = 512;
constexpr int H1 = 128, C1OUT = 128;
constexpr int H2 = 256, C2OUT = 512;
constexpr int KMAX = 64;
constexpr int QPB = 32;   // queries per conv block (2 per warp)
constexpr int MT  = 64;   // pair m-tile
constexpr int NT  = 128;  // n-tile
constexpr int KT  = 32;   // k-tile

// ---------------- scratch (__device__ globals; no allocation allowed) ----------------
// NOTE: referenced ONLY inside device code (host-side use passes host shadow!).
__device__ float g_p   [B_*N_*3];
__device__ int   g_idx1[B_*M1];
__device__ float g_pos1[B_*M1*3];
__device__ float g_P1  [B_*M1*H1];
__device__ float g_Q1  [B_*M1*H1];
__device__ float g_x1  [B_*M1*C1OUT];
__device__ int   g_idx2[B_*M2];
__device__ float g_pos2[B_*M2*3];
__device__ float g_P2  [B_*M2*H2];
__device__ float g_Q2  [B_*M2*H2];

// ---------------- normalize: per-cloud mean / unbiased std ----------------
// Sequential per-coordinate accumulation (verified passing; do not perturb).
__global__ void k_normalize(const float* __restrict__ pos) {
    int b = blockIdx.x, tid = threadIdx.x;           // 512 threads
    __shared__ float s_mean[3], s_den[3];
    const float* p = pos + b*N_*3;

    if (tid < 3) {
        float s = 0.f;
        for (int i = 0; i < N_; ++i) s = __fadd_rn(s, p[i*3 + tid]);
        s_mean[tid] = __fdiv_rn(s, (float)N_);
    }
    __syncthreads();
    if (tid < 3) {
        float mu = s_mean[tid];
        float s = 0.f;
        for (int i = 0; i < N_; ++i) {
            float d = __fsub_rn(p[i*3 + tid], mu);
            s = __fadd_rn(s, __fmul_rn(d, d));
        }
        float var = __fdiv_rn(s, (float)(N_ - 1));
        s_den[tid] = __fadd_rn(__fsqrt_rn(var), 1e-6f);
    }
    __syncthreads();
    float mx = s_mean[0], my = s_mean[1], mz = s_mean[2];
    float dx0 = s_den[0], dy0 = s_den[1], dz0 = s_den[2];
    for (int i = tid; i < N_; i += 512) {
        g_p[(b*N_+i)*3+0] = __fdiv_rn(__fsub_rn(p[i*3+0], mx), dx0);
        g_p[(b*N_+i)*3+1] = __fdiv_rn(__fsub_rn(p[i*3+1], my), dy0);
        g_p[(b*N_+i)*3+2] = __fdiv_rn(__fsub_rn(p[i*3+2], mz), dz0);
    }
}

// ---------------- farthest point sampling (R8 scheme: single barrier, double-buffered,
// redundant 2nd-stage REDUX in every warp — NO smem atomics) ----------------
// LVL==1: g_p[2048] -> g_idx1/g_pos1[1024];  LVL==2: g_pos1[1024] -> g_idx2/g_pos2[512]
template<int NP, int KSEL, int PT, int LVL>
__global__ void __launch_bounds__(512)
k_fps() {
    constexpr int T  = NP / PT;   // 512 threads
    constexpr int NW = T / 32;    // 16 warps
    const float* src   = (LVL == 1) ? g_p    : g_pos1;
    int*       idx_out = (LVL == 1) ? g_idx1 : g_idx2;
    float*     pos_out = (LVL == 1) ? g_pos1 : g_pos2;

    int b = blockIdx.x, t = threadIdx.x;
    int lane = t & 31, w = t >> 5;
    __shared__ float sx[NP], sy[NP], sz[NP];
    __shared__ unsigned wb[2][32];
    __shared__ int wi[2][32];
    __shared__ int s_hist[KSEL];
    const float* p = src + b*NP*3;

    float px[PT], py[PT], pz[PT], dd[PT];
    #pragma unroll
    for (int s=0;s<PT;s++){
        int i = t + s*T;
        float x=p[i*3+0], y=p[i*3+1], z=p[i*3+2];
        px[s]=x; py[s]=y; pz[s]=z; dd[s]=1e10f;
        sx[i]=x; sy[i]=y; sz[i]=z;
    }
    if (t < 32) { wb[0][t]=0u; wb[1][t]=0u; wi[0][t]=0x7fffffff; wi[1][t]=0x7fffffff; }
    if (t==0) s_hist[0] = 0;
    __syncthreads();

    int win = 0;                      // every thread tracks the winner locally
    for (int it=1; it<KSEL; ++it) {
        float lx=sx[win], ly=sy[win], lz=sz[win];   // broadcast LDS
        float bd = -1.f; int bi = 0;
        #pragma unroll
        for (int s=0;s<PT;s++){
            float dx=__fsub_rn(px[s],lx), dy=__fsub_rn(py[s],ly), dz=__fsub_rn(pz[s],lz);
            float d = __fadd_rn(__fadd_rn(__fmul_rn(dx,dx),__fmul_rn(dy,dy)),__fmul_rn(dz,dz));
            dd[s] = fminf(dd[s], d);
            if (dd[s] > bd) { bd = dd[s]; bi = t + s*T; }  // strict > : lowest index per thread
        }
        unsigned mybits = __float_as_uint(bd);             // dist >= 0 -> monotone bits
        unsigned mb = __reduce_max_sync(0xffffffffu, mybits);
        unsigned cand = (mybits == mb) ? (unsigned)bi : 0xffffffffu;
        unsigned mi = __reduce_min_sync(0xffffffffu, cand);
        int par = it & 1;                                   // parity double-buffer
        if (lane==0){ wb[par][w]=mb; wi[par][w]=(int)mi; }
        __syncthreads();                                    // ONLY barrier per iteration
        // redundant 2nd stage in every warp -> winner in registers, no 2nd barrier
        unsigned vb = (lane < NW) ? wb[par][lane] : 0u;
        int      vi = (lane < NW) ? wi[par][lane] : 0x7fffffff;
        unsigned mb2 = __reduce_max_sync(0xffffffffu, vb);
        unsigned cand2 = (vb==mb2) ? (unsigned)vi : 0xffffffffu;
        win = (int)__reduce_min_sync(0xffffffffu, cand2);
        if (t==0) s_hist[it] = win;
    }
    __syncthreads();
    // bulk write-out (off the serial critical path)
    for (int i = t; i < KSEL; i += T) {
        int h = s_hist[i];
        idx_out[b*KSEL+i] = h;
        pos_out[(b*KSEL+i)*3+0] = sx[h];
        pos_out[(b*KSEL+i)*3+1] = sy[h];
        pos_out[(b*KSEL+i)*3+2] = sz[h];
    }
}

// ---------------- level-1 P/Q precompute (BN folded) ----------------
__global__ void k_prep1(const float* __restrict__ w1, const float* __restrict__ b1,
                        const float* __restrict__ g, const float* __restrict__ beta,
                        const float* __restrict__ m, const float* __restrict__ v) {
    int idx = blockIdx.x*256 + threadIdx.x;
    if (idx >= B_*M1*H1) return;
    int c = idx & (H1-1), pj = idx >> 7;
    float x = g_pos1[pj*3+0], y = g_pos1[pj*3+1], z = g_pos1[pj*3+2];
    float s = g[c] / sqrtf(v[c] + 1e-5f);
    float t = beta[c] - m[c]*s;
    float wa0=w1[0*H1+c], wa1=w1[1*H1+c], wa2=w1[2*H1+c];
    float wb0=w1[3*H1+c], wb1=w1[4*H1+c], wb2=w1[5*H1+c];
    float A = x*(wa0+wb0) + y*(wa1+wb1) + z*(wa2+wb2) + b1[c];
    g_P1[idx] = A * s;
    float q = -(x*wb0 + y*wb1 + z*wb2);
    g_Q1[idx] = q * s + t;
}

// ---------------- level-2 P precompute: gathered GEMM [4096,128]@[128,256] ----------------
__global__ void k_prep2(const float* __restrict__ w1, const float* __restrict__ b1,
                        const float* __restrict__ g, const float* __restrict__ v) {
    extern __shared__ char smemraw[];
    float* xs = (float*)smemraw;            // [64][128]
    float* ws = xs + 64*128;                // [128][68] padded
    int tid = threadIdx.x;                  // 256
    int row0 = blockIdx.x * 64;             // global row in [0,4096)
    int n0   = blockIdx.y * 64;
    int b = row0 / M2;

    for (int i = tid; i < 64*128; i += 256) {
        int r = i >> 7, k = i & 127;
        int jj = g_idx2[row0 + r];
        xs[r*128 + k] = g_x1[(b*M1 + jj)*H1 + k];
    }
    for (int i = tid; i < 128*64; i += 256) {
        int k = i >> 6, nn = i & 63;
        ws[k*68 + nn] = w1[k*H2 + n0 + nn];
    }
    __syncthreads();

    int ty = tid >> 4, tx = tid & 15;
    float acc[4][4] = {};
    #pragma unroll 4
    for (int k = 0; k < 128; ++k) {
        float a0 = xs[(ty*4+0)*128 + k];
        float a1 = xs[(ty*4+1)*128 + k];
        float a2 = xs[(ty*4+2)*128 + k];
        float a3 = xs[(ty*4+3)*128 + k];
        float4 bv = *(const float4*)&ws[k*68 + tx*4];
        acc[0][0]+=a0*bv.x; acc[0][1]+=a0*bv.y; acc[0][2]+=a0*bv.z; acc[0][3]+=a0*bv.w;
        acc[1][0]+=a1*bv.x; acc[1][1]+=a1*bv.y; acc[1][2]+=a1*bv.z; acc[1][3]+=a1*bv.w;
        acc[2][0]+=a2*bv.x; acc[2][1]+=a2*bv.y; acc[2][2]+=a2*bv.z; acc[2][3]+=a2*bv.w;
        acc[3][0]+=a3*bv.x; acc[3][1]+=a3*bv.y; acc[3][2]+=a3*bv.z; acc[3][3]+=a3*bv.w;
    }
    #pragma unroll
    for (int mi=0; mi<4; ++mi) {
        int r = row0 + ty*4 + mi;
        float px = g_pos2[r*3+0], py = g_pos2[r*3+1], pz = g_pos2[r*3+2];
        #pragma unroll
        for (int ni=0; ni<4; ++ni) {
            int n = n0 + tx*4 + ni;
            float s = g[n] / sqrtf(v[n] + 1e-5f);
            float A = acc[mi][ni]
                    + px*w1[128*H2 + n] + py*w1[129*H2 + n] + pz*w1[130*H2 + n] + b1[n];
            g_P2[r*H2 + n] = A * s;
        }
    }
}

__global__ void k_prep2q(const float* __restrict__ w1, const float* __restrict__ g,
                         const float* __restrict__ beta, const float* __restrict__ m,
                         const float* __restrict__ v) {
    int idx = blockIdx.x*256 + threadIdx.x;
    if (idx >= B_*M2*H2) return;
    int c = idx & (H2-1), pj = idx >> 8;
    float x = g_pos2[pj*3+0], y = g_pos2[pj*3+1], z = g_pos2[pj*3+2];
    float s = g[c] / sqrtf(v[c] + 1e-5f);
    float t = beta[c] - m[c]*s;
    float q = -(x*w1[128*H2+c] + y*w1[129*H2+c] + z*w1[130*H2+c]);
    g_Q2[idx] = q * s + t;
}

// ---------------- ball-query + pair-list GEMM + max aggregation ----------------
constexpr size_t conv_smem_bytes(int MSRC, int HDIM, int COUT) {
    return (size_t)(MSRC*3 + QPB*KMAX + QPB*KMAX + QPB + QPB*KMAX + QPB*KMAX + 64
                    + MT*HDIM + KT*(NT+4) + QPB*COUT) * 4;
}

template<int MSRC, int HDIM, int COUT, int LVL>
__global__ void __launch_bounds__(512)
k_conv(const float* __restrict__ w2, const float* __restrict__ b2,
       float* __restrict__ out_ext, float R2) {
    const float* srcpos = (LVL == 1) ? g_pos1 : g_pos2;
    const float* P      = (LVL == 1) ? g_P1   : g_P2;
    const float* Q      = (LVL == 1) ? g_Q1   : g_Q2;
    float*       out    = (LVL == 1) ? g_x1   : out_ext;

    extern __shared__ char smemraw[];
    float*    s_pos = (float*)smemraw;                 // MSRC*3
    float*    s_pd  = s_pos + MSRC*3;                  // QPB*KMAX
    int*      s_pj  = (int*)(s_pd + QPB*KMAX);         // QPB*KMAX
    int*      s_cnt = s_pj + QPB*KMAX;                 // QPB
    int*      s_fi  = s_cnt + QPB;                     // QPB*KMAX
    int*      s_fj  = s_fi + QPB*KMAX;                 // QPB*KMAX
    int*      s_qoff= s_fj + QPB*KMAX;                 // 64
    float*    s_h   = (float*)(s_qoff + 64);           // MT*HDIM
    float*    s_w   = s_h + MT*HDIM;                   // KT*(NT+4)
    unsigned* s_out = (unsigned*)(s_w + KT*(NT+4));    // QPB*COUT

    int blk = blockIdx.x;
    int b  = blk / (MSRC/QPB);
    int q0 = (blk % (MSRC/QPB)) * QPB;
    int tid = threadIdx.x, lane = tid & 31, w = tid >> 5;

    for (int i = tid; i < MSRC*3; i += 512) s_pos[i] = srcpos[b*MSRC*3 + i];
    __syncthreads();

    // ---- pair build: warp w handles queries q0+2w, q0+2w+1 ----
    for (int qq = 0; qq < 2; ++qq) {
        int qslot = w*2 + qq;
        int qi = q0 + qslot;
        float qx = s_pos[qi*3+0], qy = s_pos[qi*3+1], qz = s_pos[qi*3+2];
        int cnt = 0;
        for (int base = 0; base < MSRC; base += 32) {
            int j = base + lane;
            float dx = __fsub_rn(s_pos[j*3+0], qx);
            float dy = __fsub_rn(s_pos[j*3+1], qy);
            float dz = __fsub_rn(s_pos[j*3+2], qz);
            float d2 = __fadd_rn(__fadd_rn(__fmul_rn(dx,dx),__fmul_rn(dy,dy)),__fmul_rn(dz,dz));
            bool pred = (d2 <= R2);
            unsigned ball = __ballot_sync(0xffffffffu, pred);
            int nb = __popc(ball);
            if (cnt + nb <= KMAX) {
                if (pred) {
                    int pos = cnt + __popc(ball & ((1u<<lane)-1u));
                    s_pj[qslot*KMAX+pos] = j; s_pd[qslot*KMAX+pos] = d2;
                }
                cnt += nb;
            } else {
                // rare slow path: keep K smallest d2 (ties -> lower j kept)
                unsigned rem = ball;
                while (rem) {
                    int l = __ffs(rem)-1; rem &= rem-1u;
                    float cd2 = __shfl_sync(0xffffffffu, d2, l);
                    int cj = base + l;
                    if (cnt < KMAX) {
                        if (lane==0){ s_pj[qslot*KMAX+cnt]=cj; s_pd[qslot*KMAX+cnt]=cd2; }
                        cnt++;
                    } else {
                        float e0 = s_pd[qslot*KMAX+lane],    e1 = s_pd[qslot*KMAX+32+lane];
                        int   j0 = s_pj[qslot*KMAX+lane],    j1 = s_pj[qslot*KMAX+32+lane];
                        float md; int ms, mj;
                        if (e1 > e0 || (e1==e0 && j1>j0)) { md=e1; ms=32+lane; mj=j1; }
                        else                               { md=e0; ms=lane;    mj=j0; }
                        #pragma unroll
                        for (int o=16;o;o>>=1){
                            float od = __shfl_xor_sync(~0u, md, o);
                            int   os = __shfl_xor_sync(~0u, ms, o);
                            int   oj = __shfl_xor_sync(~0u, mj, o);
                            if (od > md || (od==md && oj>mj)) { md=od; ms=os; mj=oj; }
                        }
                        if (cd2 < md) {
                            if (lane==0){ s_pj[qslot*KMAX+ms]=cj; s_pd[qslot*KMAX+ms]=cd2; }
                        }
                    }
                    __syncwarp();
                }
            }
        }
        if (lane==0) s_cnt[qslot] = cnt;
    }
    __syncthreads();

    if (tid==0){
        int acc=0;
        for (int i=0;i<QPB;i++){ s_qoff[i]=acc; acc+=s_cnt[i]; }
        s_qoff[QPB]=acc;
    }
    __syncthreads();
    for (int qq = 0; qq < 2; ++qq) {
        int qslot = w*2 + qq;
        int off = s_qoff[qslot], c = s_cnt[qslot];
        for (int e = lane; e < c; e += 32){ s_fi[off+e]=qslot; s_fj[off+e]=s_pj[qslot*KMAX+e]; }
    }
    for (int i = tid; i < QPB*COUT; i += 512) s_out[i] = 0u;
    __syncthreads();

    int total = s_qoff[QPB];
    int ty = tid >> 5, tx = tid & 31;

    for (int m0 = 0; m0 < total; m0 += MT) {
        // hidden tile: h = relu(P_j + Q_i)
        for (int i = tid; i < MT*HDIM; i += 512) {
            int mp = i / HDIM, k = i % HDIM;
            float val = 0.f;
            if (m0 + mp < total) {
                int qi = s_fi[m0+mp], j = s_fj[m0+mp];
                val = fmaxf(P[(size_t)(b*MSRC + j)*HDIM + k] + Q[(size_t)(b*MSRC + q0 + qi)*HDIM + k], 0.f);
            }
            s_h[i] = val;
        }
        __syncthreads();

        for (int n0 = 0; n0 < COUT; n0 += NT) {
            float acc[4][4] = {};
            for (int k0 = 0; k0 < HDIM; k0 += KT) {
                for (int i = tid; i < KT*NT; i += 512) {
                    int kk = i / NT, nn = i % NT;
                    s_w[kk*(NT+4)+nn] = w2[(size_t)(k0+kk)*COUT + n0 + nn];
                }
                __syncthreads();
                #pragma unroll
                for (int kk = 0; kk < KT; ++kk) {
                    float a0 = s_h[(ty*4+0)*HDIM + k0+kk];
                    float a1 = s_h[(ty*4+1)*HDIM + k0+kk];
                    float a2 = s_h[(ty*4+2)*HDIM + k0+kk];
                    float a3 = s_h[(ty*4+3)*HDIM + k0+kk];
                    float4 bv = *(const float4*)&s_w[kk*(NT+4) + tx*4];
                    acc[0][0]+=a0*bv.x; acc[0][1]+=a0*bv.y; acc[0][2]+=a0*bv.z; acc[0][3]+=a0*bv.w;
                    acc[1][0]+=a1*bv.x; acc[1][1]+=a1*bv.y; acc[1][2]+=a1*bv.z; acc[1][3]+=a1*bv.w;
                    acc[2][0]+=a2*bv.x; acc[2][1]+=a2*bv.y; acc[2][2]+=a2*bv.z; acc[2][3]+=a2*bv.w;
                    acc[3][0]+=a3*bv.x; acc[3][1]+=a3*bv.y; acc[3][2]+=a3*bv.z; acc[3][3]+=a3*bv.w;
                }
                __syncthreads();
            }
            #pragma unroll
            for (int mi=0; mi<4; ++mi) {
                int mp = ty*4 + mi;
                if (m0 + mp < total) {
                    int qi = s_fi[m0+mp];
                    #pragma unroll
                    for (int ni=0; ni<4; ++ni) {
                        int n = n0 + tx*4 + ni;
                        float val = fmaxf(acc[mi][ni] + b2[n], 0.f);
                        atomicMax(&s_out[qi*COUT + n], __float_as_uint(val));
                    }
                }
            }
            __syncthreads();
        }
    }

    for (int i = tid; i < QPB*COUT; i += 512) {
        int q = i / COUT, c = i % COUT;
        out[(size_t)(b*MSRC + q0 + q)*COUT + c] = __uint_as_float(s_out[i]);
    }
}

// batch2: second output written as float32 into the shared float output buffer.
__global__ void k_batch2(float* __restrict__ out) {
    int i = blockIdx.x*256 + threadIdx.x;
    if (i < B_*M2) out[i] = (float)(i >> 9);   // batch id 0..7
}

// ---------------- launch ----------------
extern "C" void kernel_launch(void* const* d_in, const int* in_sizes, int n_in,
                              void* d_out, int out_size) {
    const float *pos, *c1_w1, *c1_b1, *c1_g, *c1_be, *c1_m, *c1_v, *c1_w2, *c1_b2;
    const float *c2_w1, *c2_b1, *c2_g, *c2_be, *c2_m, *c2_v, *c2_w2, *c2_b2;
    if (in_sizes[0] == B_*N_*3) {
        // setup_inputs insertion order
        pos   = (const float*)d_in[0];
        c1_w1 = (const float*)d_in[1];  c1_b1 = (const float*)d_in[2];
        c1_g  = (const float*)d_in[3];  c1_be = (const float*)d_in[4];
        c1_m  = (const float*)d_in[5];  c1_v  = (const float*)d_in[6];
        c1_w2 = (const float*)d_in[7];  c1_b2 = (const float*)d_in[8];
        c2_w1 = (const float*)d_in[9];  c2_b1 = (const float*)d_in[10];
        c2_g  = (const float*)d_in[11]; c2_be = (const float*)d_in[12];
        c2_m  = (const float*)d_in[13]; c2_v  = (const float*)d_in[14];
        c2_w2 = (const float*)d_in[15]; c2_b2 = (const float*)d_in[16];
    } else {
        // alphabetical fallback
        c1_b1 = (const float*)d_in[1];  c1_b2 = (const float*)d_in[2];
        c1_be = (const float*)d_in[3];  c1_g  = (const float*)d_in[4];
        c1_m  = (const float*)d_in[5];  c1_v  = (const float*)d_in[6];
        c1_w1 = (const float*)d_in[7];  c1_w2 = (const float*)d_in[8];
        c2_b1 = (const float*)d_in[9];  c2_b2 = (const float*)d_in[10];
        c2_be = (const float*)d_in[11]; c2_g  = (const float*)d_in[12];
        c2_m  = (const float*)d_in[13]; c2_v  = (const float*)d_in[14];
        c2_w1 = (const float*)d_in[15]; c2_w2 = (const float*)d_in[16];
        pos   = (const float*)d_in[17];
    }
    float* out = (float*)d_out;

    const size_t smem1 = conv_smem_bytes(M1, H1, C1OUT);
    const size_t smem2 = conv_smem_bytes(M2, H2, C2OUT);
    const size_t smemP2 = (64*128 + 128*68) * sizeof(float);
    cudaFuncSetAttribute(k_conv<M1,H1,C1OUT,1>, cudaFuncAttributeMaxDynamicSharedMemorySize, (int)smem1);
    cudaFuncSetAttribute(k_conv<M2,H2,C2OUT,2>, cudaFuncAttributeMaxDynamicSharedMemorySize, (int)smem2);
    cudaFuncSetAttribute(k_prep2, cudaFuncAttributeMaxDynamicSharedMemorySize, (int)smemP2);

    // Fork a side stream so fps2 overlaps prep1+conv1 (both depend only on fps1).
    cudaStream_t s2;
    cudaStreamCreateWithFlags(&s2, cudaStreamNonBlocking);
    cudaEvent_t e1, e2;
    cudaEventCreateWithFlags(&e1, cudaEventDisableTiming);
    cudaEventCreateWithFlags(&e2, cudaEventDisableTiming);

    k_normalize<<<B_, 512>>>(pos);
    k_fps<N_, M1, 4, 1><<<B_, 512>>>();

    cudaEventRecord(e1, 0);
    cudaStreamWaitEvent(s2, e1, 0);
    // side stream: batch2 (independent) + fps2 (needs only g_pos1)
    if ((size_t)out_size >= (size_t)B_*M2*C2OUT + B_*M2) {
        k_batch2<<<(B_*M2 + 255)/256, 256, 0, s2>>>(out + (size_t)B_*M2*C2OUT);
    }
    k_fps<M1, M2, 2, 2><<<B_, 512, 0, s2>>>();

    // main stream: level-1 conv pipeline
    k_prep1<<<(B_*M1*H1 + 255)/256, 256>>>(c1_w1, c1_b1, c1_g, c1_be, c1_m, c1_v);
    {
        float r2 = (float)(0.1 * 0.1);   // matches JAX f32 scalar exactly
        k_conv<M1,H1,C1OUT,1><<<B_*(M1/QPB), 512, smem1>>>(c1_w2, c1_b2, nullptr, r2);
    }

    cudaEventRecord(e2, s2);
    cudaStreamWaitEvent(0, e2, 0);

    k_prep2<<<dim3(B_*M2/64, H2/64), 256, smemP2>>>(c2_w1, c2_b1, c2_g, c2_v);
    k_prep2q<<<(B_*M2*H2 + 255)/256, 256>>>(c2_w1, c2_g, c2_be, c2_m, c2_v);
    {
        float r2 = (float)(0.25 * 0.25);
        k_conv<M2,H2,C2OUT,2><<<B_*(M2/QPB), 512, smem2>>>(c2_w2, c2_b2, out, r2);
    }

    cudaEventDestroy(e1);
    cudaEventDestroy(e2);
    cudaStreamDestroy(s2);
    (void)in_sizes; (void)n_in;
}

// round 13
// speedup vs baseline: 1.9559x; 1.3300x over previous
#include <cuda_runtime.h>
#include <cuda_bf16.h>
#include <math.h>

// Problem constants
constexpr int B_ = 8, N_ = 2048;
constexpr int M1 = 1024, M2 = 512;
constexpr int H1 = 128, C1OUT = 128;
constexpr int H2 = 256, C2OUT = 512;
constexpr int KMAX = 64;
constexpr int QPB = 32;   // queries per conv block (2 per warp)
constexpr int MT  = 64;   // pair m-tile
constexpr int NT  = 128;  // n-tile
constexpr int KT  = 32;   // k-tile
constexpr int CONV1_BLOCKS = B_*(M1/QPB);   // 256

// ---------------- scratch (__device__ globals; device-code references ONLY) ----------------
__device__ int   g_idx1[B_*M1];
__device__ float g_pos1[B_*M1*3];
__device__ float g_P1  [B_*M1*H1];
__device__ float g_Q1  [B_*M1*H1];
__device__ float g_x1  [B_*M1*C1OUT];
__device__ int   g_idx2[B_*M2];
__device__ float g_pos2[B_*M2*3];
__device__ float g_P2  [B_*M2*H2];
__device__ float g_Q2  [B_*M2*H2];

// ---------------- fused normalize + FPS level 1 ----------------
// Block b: sequentially normalize batch b (bit-identical to reference), then run
// the R8 single-barrier FPS over the normalized points (never touching DRAM for them).
__global__ void __launch_bounds__(512)
k_norm_fps1(const float* __restrict__ pos) {
    constexpr int NP = N_, KSEL = M1, PT = 4, T = 512, NW = T/32;
    int b = blockIdx.x, t = threadIdx.x;
    int lane = t & 31, w = t >> 5;
    __shared__ float sx[NP], sy[NP], sz[NP];
    __shared__ float s_mean[3], s_den[3];
    __shared__ unsigned wb[2][32];
    __shared__ int wi[2][32];
    __shared__ int s_hist[KSEL];
    const float* p = pos + b*NP*3;

    // normalize: strictly sequential accumulation per coordinate (matches XLA)
    if (t < 3) {
        float s = 0.f;
        for (int i = 0; i < NP; ++i) s = __fadd_rn(s, p[i*3 + t]);
        s_mean[t] = __fdiv_rn(s, (float)NP);
    }
    __syncthreads();
    if (t < 3) {
        float mu = s_mean[t];
        float s = 0.f;
        for (int i = 0; i < NP; ++i) {
            float d = __fsub_rn(p[i*3 + t], mu);
            s = __fadd_rn(s, __fmul_rn(d, d));
        }
        float var = __fdiv_rn(s, (float)(NP - 1));
        s_den[t] = __fadd_rn(__fsqrt_rn(var), 1e-6f);
    }
    __syncthreads();
    float mx = s_mean[0], my = s_mean[1], mz = s_mean[2];
    float dx0 = s_den[0], dy0 = s_den[1], dz0 = s_den[2];

    float px[PT], py[PT], pz[PT], dd[PT];
    #pragma unroll
    for (int s=0;s<PT;s++){
        int i = t + s*T;
        float x = __fdiv_rn(__fsub_rn(p[i*3+0], mx), dx0);
        float y = __fdiv_rn(__fsub_rn(p[i*3+1], my), dy0);
        float z = __fdiv_rn(__fsub_rn(p[i*3+2], mz), dz0);
        px[s]=x; py[s]=y; pz[s]=z; dd[s]=1e10f;
        sx[i]=x; sy[i]=y; sz[i]=z;
    }
    if (t < 32) { wb[0][t]=0u; wb[1][t]=0u; wi[0][t]=0x7fffffff; wi[1][t]=0x7fffffff; }
    if (t==0) s_hist[0] = 0;
    __syncthreads();

    int win = 0;
    for (int it=1; it<KSEL; ++it) {
        float lx=sx[win], ly=sy[win], lz=sz[win];
        float bd = -1.f; int bi = 0;
        #pragma unroll
        for (int s=0;s<PT;s++){
            float dx=__fsub_rn(px[s],lx), dy=__fsub_rn(py[s],ly), dz=__fsub_rn(pz[s],lz);
            float d = __fadd_rn(__fadd_rn(__fmul_rn(dx,dx),__fmul_rn(dy,dy)),__fmul_rn(dz,dz));
            dd[s] = fminf(dd[s], d);
            if (dd[s] > bd) { bd = dd[s]; bi = t + s*T; }
        }
        unsigned mybits = __float_as_uint(bd);
        unsigned mb = __reduce_max_sync(0xffffffffu, mybits);
        unsigned cand = (mybits == mb) ? (unsigned)bi : 0xffffffffu;
        unsigned mi = __reduce_min_sync(0xffffffffu, cand);
        int par = it & 1;
        if (lane==0){ wb[par][w]=mb; wi[par][w]=(int)mi; }
        __syncthreads();
        unsigned vb = (lane < NW) ? wb[par][lane] : 0u;
        int      vi = (lane < NW) ? wi[par][lane] : 0x7fffffff;
        unsigned mb2 = __reduce_max_sync(0xffffffffu, vb);
        unsigned cand2 = (vb==mb2) ? (unsigned)vi : 0xffffffffu;
        win = (int)__reduce_min_sync(0xffffffffu, cand2);
        if (t==0) s_hist[it] = win;
    }
    __syncthreads();
    for (int i = t; i < KSEL; i += T) {
        int h = s_hist[i];
        g_idx1[b*KSEL+i] = h;
        g_pos1[(b*KSEL+i)*3+0] = sx[h];
        g_pos1[(b*KSEL+i)*3+1] = sy[h];
        g_pos1[(b*KSEL+i)*3+2] = sz[h];
    }
}

// ---------------- FPS body (used for level 2, smem carved from dynamic) ----------------
template<int NP, int KSEL, int PT>
__device__ __forceinline__ void fps_body(char* smemraw, int b,
                                         const float* __restrict__ src,
                                         int* __restrict__ idx_out,
                                         float* __restrict__ pos_out) {
    constexpr int T = 512, NW = T/32;
    float*    sx = (float*)smemraw;
    float*    sy = sx + NP;
    float*    sz = sy + NP;
    unsigned* wb = (unsigned*)(sz + NP);       // [2][32]
    int*      wi = (int*)(wb + 64);            // [2][32]
    int*  s_hist = wi + 64;                    // [KSEL]

    int t = threadIdx.x, lane = t & 31, w = t >> 5;
    const float* p = src + b*NP*3;

    float px[PT], py[PT], pz[PT], dd[PT];
    #pragma unroll
    for (int s=0;s<PT;s++){
        int i = t + s*T;
        float x=p[i*3+0], y=p[i*3+1], z=p[i*3+2];
        px[s]=x; py[s]=y; pz[s]=z; dd[s]=1e10f;
        sx[i]=x; sy[i]=y; sz[i]=z;
    }
    if (t < 32) { wb[t]=0u; wb[32+t]=0u; wi[t]=0x7fffffff; wi[32+t]=0x7fffffff; }
    if (t==0) s_hist[0] = 0;
    __syncthreads();

    int win = 0;
    for (int it=1; it<KSEL; ++it) {
        float lx=sx[win], ly=sy[win], lz=sz[win];
        float bd = -1.f; int bi = 0;
        #pragma unroll
        for (int s=0;s<PT;s++){
            float dx=__fsub_rn(px[s],lx), dy=__fsub_rn(py[s],ly), dz=__fsub_rn(pz[s],lz);
            float d = __fadd_rn(__fadd_rn(__fmul_rn(dx,dx),__fmul_rn(dy,dy)),__fmul_rn(dz,dz));
            dd[s] = fminf(dd[s], d);
            if (dd[s] > bd) { bd = dd[s]; bi = t + s*T; }
        }
        unsigned mybits = __float_as_uint(bd);
        unsigned mb = __reduce_max_sync(0xffffffffu, mybits);
        unsigned cand = (mybits == mb) ? (unsigned)bi : 0xffffffffu;
        unsigned mi = __reduce_min_sync(0xffffffffu, cand);
        int par = it & 1;
        if (lane==0){ wb[par*32+w]=mb; wi[par*32+w]=(int)mi; }
        __syncthreads();
        unsigned vb = (lane < NW) ? wb[par*32+lane] : 0u;
        int      vi = (lane < NW) ? wi[par*32+lane] : 0x7fffffff;
        unsigned mb2 = __reduce_max_sync(0xffffffffu, vb);
        unsigned cand2 = (vb==mb2) ? (unsigned)vi : 0xffffffffu;
        win = (int)__reduce_min_sync(0xffffffffu, cand2);
        if (t==0) s_hist[it] = win;
    }
    __syncthreads();
    for (int i = t; i < KSEL; i += 512) {
        int h = s_hist[i];
        idx_out[b*KSEL+i] = h;
        pos_out[(b*KSEL+i)*3+0] = sx[h];
        pos_out[(b*KSEL+i)*3+1] = sy[h];
        pos_out[(b*KSEL+i)*3+2] = sz[h];
    }
}

// ---------------- level-1 P/Q precompute (BN folded) ----------------
__global__ void k_prep1(const float* __restrict__ w1, const float* __restrict__ b1,
                        const float* __restrict__ g, const float* __restrict__ beta,
                        const float* __restrict__ m, const float* __restrict__ v) {
    int idx = blockIdx.x*256 + threadIdx.x;
    if (idx >= B_*M1*H1) return;
    int c = idx & (H1-1), pj = idx >> 7;
    float x = g_pos1[pj*3+0], y = g_pos1[pj*3+1], z = g_pos1[pj*3+2];
    float s = g[c] / sqrtf(v[c] + 1e-5f);
    float t = beta[c] - m[c]*s;
    float wa0=w1[0*H1+c], wa1=w1[1*H1+c], wa2=w1[2*H1+c];
    float wb0=w1[3*H1+c], wb1=w1[4*H1+c], wb2=w1[5*H1+c];
    float A = x*(wa0+wb0) + y*(wa1+wb1) + z*(wa2+wb2) + b1[c];
    g_P1[idx] = A * s;
    float q = -(x*wb0 + y*wb1 + z*wb2);
    g_Q1[idx] = q * s + t;
}

// ---------------- level-2 P precompute: gathered GEMM [4096,128]@[128,256] ----------------
__global__ void k_prep2(const float* __restrict__ w1, const float* __restrict__ b1,
                        const float* __restrict__ g, const float* __restrict__ v) {
    extern __shared__ char smemraw[];
    float* xs = (float*)smemraw;            // [64][128]
    float* ws = xs + 64*128;                // [128][68] padded
    int tid = threadIdx.x;                  // 256
    int row0 = blockIdx.x * 64;
    int n0   = blockIdx.y * 64;
    int b = row0 / M2;

    for (int i = tid; i < 64*128; i += 256) {
        int r = i >> 7, k = i & 127;
        int jj = g_idx2[row0 + r];
        xs[r*128 + k] = g_x1[(b*M1 + jj)*H1 + k];
    }
    for (int i = tid; i < 128*64; i += 256) {
        int k = i >> 6, nn = i & 63;
        ws[k*68 + nn] = w1[k*H2 + n0 + nn];
    }
    __syncthreads();

    int ty = tid >> 4, tx = tid & 15;
    float acc[4][4] = {};
    #pragma unroll 4
    for (int k = 0; k < 128; ++k) {
        float a0 = xs[(ty*4+0)*128 + k];
        float a1 = xs[(ty*4+1)*128 + k];
        float a2 = xs[(ty*4+2)*128 + k];
        float a3 = xs[(ty*4+3)*128 + k];
        float4 bv = *(const float4*)&ws[k*68 + tx*4];
        acc[0][0]+=a0*bv.x; acc[0][1]+=a0*bv.y; acc[0][2]+=a0*bv.z; acc[0][3]+=a0*bv.w;
        acc[1][0]+=a1*bv.x; acc[1][1]+=a1*bv.y; acc[1][2]+=a1*bv.z; acc[1][3]+=a1*bv.w;
        acc[2][0]+=a2*bv.x; acc[2][1]+=a2*bv.y; acc[2][2]+=a2*bv.z; acc[2][3]+=a2*bv.w;
        acc[3][0]+=a3*bv.x; acc[3][1]+=a3*bv.y; acc[3][2]+=a3*bv.z; acc[3][3]+=a3*bv.w;
    }
    #pragma unroll
    for (int mi=0; mi<4; ++mi) {
        int r = row0 + ty*4 + mi;
        float px = g_pos2[r*3+0], py = g_pos2[r*3+1], pz = g_pos2[r*3+2];
        #pragma unroll
        for (int ni=0; ni<4; ++ni) {
            int n = n0 + tx*4 + ni;
            float s = g[n] / sqrtf(v[n] + 1e-5f);
            float A = acc[mi][ni]
                    + px*w1[128*H2 + n] + py*w1[129*H2 + n] + pz*w1[130*H2 + n] + b1[n];
            g_P2[r*H2 + n] = A * s;
        }
    }
}

__global__ void k_prep2q(const float* __restrict__ w1, const float* __restrict__ g,
                         const float* __restrict__ beta, const float* __restrict__ m,
                         const float* __restrict__ v) {
    int idx = blockIdx.x*256 + threadIdx.x;
    if (idx >= B_*M2*H2) return;
    int c = idx & (H2-1), pj = idx >> 8;
    float x = g_pos2[pj*3+0], y = g_pos2[pj*3+1], z = g_pos2[pj*3+2];
    float s = g[c] / sqrtf(v[c] + 1e-5f);
    float t = beta[c] - m[c]*s;
    float q = -(x*w1[128*H2+c] + y*w1[129*H2+c] + z*w1[130*H2+c]);
    g_Q2[idx] = q * s + t;
}

// ---------------- ball-query + pair-list GEMM + max aggregation (device body) ----------------
constexpr size_t conv_smem_bytes(int MSRC, int HDIM, int COUT) {
    return (size_t)(MSRC*3 + QPB*KMAX + QPB*KMAX + QPB + QPB*KMAX + QPB*KMAX + 64
                    + MT*HDIM + KT*(NT+4) + QPB*COUT) * 4;
}

template<int MSRC, int HDIM, int COUT>
__device__ __forceinline__ void conv_body(char* smemraw, int blk,
        const float* __restrict__ srcpos, const float* __restrict__ P,
        const float* __restrict__ Q, const float* __restrict__ w2,
        const float* __restrict__ b2, float* __restrict__ out, float R2) {
    float*    s_pos = (float*)smemraw;                 // MSRC*3
    float*    s_pd  = s_pos + MSRC*3;                  // QPB*KMAX
    int*      s_pj  = (int*)(s_pd + QPB*KMAX);         // QPB*KMAX
    int*      s_cnt = s_pj + QPB*KMAX;                 // QPB
    int*      s_fi  = s_cnt + QPB;                     // QPB*KMAX
    int*      s_fj  = s_fi + QPB*KMAX;                 // QPB*KMAX
    int*      s_qoff= s_fj + QPB*KMAX;                 // 64
    float*    s_h   = (float*)(s_qoff + 64);           // MT*HDIM
    float*    s_w   = s_h + MT*HDIM;                   // KT*(NT+4)
    unsigned* s_out = (unsigned*)(s_w + KT*(NT+4));    // QPB*COUT

    int b  = blk / (MSRC/QPB);
    int q0 = (blk % (MSRC/QPB)) * QPB;
    int tid = threadIdx.x, lane = tid & 31, w = tid >> 5;

    for (int i = tid; i < MSRC*3; i += 512) s_pos[i] = srcpos[b*MSRC*3 + i];
    __syncthreads();

    for (int qq = 0; qq < 2; ++qq) {
        int qslot = w*2 + qq;
        int qi = q0 + qslot;
        float qx = s_pos[qi*3+0], qy = s_pos[qi*3+1], qz = s_pos[qi*3+2];
        int cnt = 0;
        for (int base = 0; base < MSRC; base += 32) {
            int j = base + lane;
            float dx = __fsub_rn(s_pos[j*3+0], qx);
            float dy = __fsub_rn(s_pos[j*3+1], qy);
            float dz = __fsub_rn(s_pos[j*3+2], qz);
            float d2 = __fadd_rn(__fadd_rn(__fmul_rn(dx,dx),__fmul_rn(dy,dy)),__fmul_rn(dz,dz));
            bool pred = (d2 <= R2);
            unsigned ball = __ballot_sync(0xffffffffu, pred);
            int nb = __popc(ball);
            if (cnt + nb <= KMAX) {
                if (pred) {
                    int pos = cnt + __popc(ball & ((1u<<lane)-1u));
                    s_pj[qslot*KMAX+pos] = j; s_pd[qslot*KMAX+pos] = d2;
                }
                cnt += nb;
            } else {
                unsigned rem = ball;
                while (rem) {
                    int l = __ffs(rem)-1; rem &= rem-1u;
                    float cd2 = __shfl_sync(0xffffffffu, d2, l);
                    int cj = base + l;
                    if (cnt < KMAX) {
                        if (lane==0){ s_pj[qslot*KMAX+cnt]=cj; s_pd[qslot*KMAX+cnt]=cd2; }
                        cnt++;
                    } else {
                        float e0 = s_pd[qslot*KMAX+lane],    e1 = s_pd[qslot*KMAX+32+lane];
                        int   j0 = s_pj[qslot*KMAX+lane],    j1 = s_pj[qslot*KMAX+32+lane];
                        float md; int ms, mj;
                        if (e1 > e0 || (e1==e0 && j1>j0)) { md=e1; ms=32+lane; mj=j1; }
                        else                               { md=e0; ms=lane;    mj=j0; }
                        #pragma unroll
                        for (int o=16;o;o>>=1){
                            float od = __shfl_xor_sync(~0u, md, o);
                            int   os = __shfl_xor_sync(~0u, ms, o);
                            int   oj = __shfl_xor_sync(~0u, mj, o);
                            if (od > md || (od==md && oj>mj)) { md=od; ms=os; mj=oj; }
                        }
                        if (cd2 < md) {
                            if (lane==0){ s_pj[qslot*KMAX+ms]=cj; s_pd[qslot*KMAX+ms]=cd2; }
                        }
                    }
                    __syncwarp();
                }
            }
        }
        if (lane==0) s_cnt[qslot] = cnt;
    }
    __syncthreads();

    if (tid==0){
        int acc=0;
        for (int i=0;i<QPB;i++){ s_qoff[i]=acc; acc+=s_cnt[i]; }
        s_qoff[QPB]=acc;
    }
    __syncthreads();
    for (int qq = 0; qq < 2; ++qq) {
        int qslot = w*2 + qq;
        int off = s_qoff[qslot], c = s_cnt[qslot];
        for (int e = lane; e < c; e += 32){ s_fi[off+e]=qslot; s_fj[off+e]=s_pj[qslot*KMAX+e]; }
    }
    for (int i = tid; i < QPB*COUT; i += 512) s_out[i] = 0u;
    __syncthreads();

    int total = s_qoff[QPB];
    int ty = tid >> 5, tx = tid & 31;

    for (int m0 = 0; m0 < total; m0 += MT) {
        for (int i = tid; i < MT*HDIM; i += 512) {
            int mp = i / HDIM, k = i % HDIM;
            float val = 0.f;
            if (m0 + mp < total) {
                int qi = s_fi[m0+mp], j = s_fj[m0+mp];
                val = fmaxf(P[(size_t)(b*MSRC + j)*HDIM + k] + Q[(size_t)(b*MSRC + q0 + qi)*HDIM + k], 0.f);
            }
            s_h[i] = val;
        }
        __syncthreads();

        for (int n0 = 0; n0 < COUT; n0 += NT) {
            float acc[4][4] = {};
            for (int k0 = 0; k0 < HDIM; k0 += KT) {
                for (int i = tid; i < KT*NT; i += 512) {
                    int kk = i / NT, nn = i % NT;
                    s_w[kk*(NT+4)+nn] = w2[(size_t)(k0+kk)*COUT + n0 + nn];
                }
                __syncthreads();
                #pragma unroll
                for (int kk = 0; kk < KT; ++kk) {
                    float a0 = s_h[(ty*4+0)*HDIM + k0+kk];
                    float a1 = s_h[(ty*4+1)*HDIM + k0+kk];
                    float a2 = s_h[(ty*4+2)*HDIM + k0+kk];
                    float a3 = s_h[(ty*4+3)*HDIM + k0+kk];
                    float4 bv = *(const float4*)&s_w[kk*(NT+4) + tx*4];
                    acc[0][0]+=a0*bv.x; acc[0][1]+=a0*bv.y; acc[0][2]+=a0*bv.z; acc[0][3]+=a0*bv.w;
                    acc[1][0]+=a1*bv.x; acc[1][1]+=a1*bv.y; acc[1][2]+=a1*bv.z; acc[1][3]+=a1*bv.w;
                    acc[2][0]+=a2*bv.x; acc[2][1]+=a2*bv.y; acc[2][2]+=a2*bv.z; acc[2][3]+=a2*bv.w;
                    acc[3][0]+=a3*bv.x; acc[3][1]+=a3*bv.y; acc[3][2]+=a3*bv.z; acc[3][3]+=a3*bv.w;
                }
                __syncthreads();
            }
            #pragma unroll
            for (int mi=0; mi<4; ++mi) {
                int mp = ty*4 + mi;
                if (m0 + mp < total) {
                    int qi = s_fi[m0+mp];
                    #pragma unroll
                    for (int ni=0; ni<4; ++ni) {
                        int n = n0 + tx*4 + ni;
                        float val = fmaxf(acc[mi][ni] + b2[n], 0.f);
                        atomicMax(&s_out[qi*COUT + n], __float_as_uint(val));
                    }
                }
            }
            __syncthreads();
        }
    }

    for (int i = tid; i < QPB*COUT; i += 512) {
        int q = i / COUT, c = i % COUT;
        out[(size_t)(b*MSRC + q0 + q)*COUT + c] = __uint_as_float(s_out[i]);
    }
}

// ---------------- fused conv1 + fps2 + batch2 (single-kernel overlap, no streams) ----------------
__global__ void __launch_bounds__(512)
k_conv1_fps2(const float* __restrict__ w2, const float* __restrict__ b2,
             float* __restrict__ batch_out, float R2) {
    extern __shared__ char smemraw[];
    if (blockIdx.x < CONV1_BLOCKS) {
        conv_body<M1,H1,C1OUT>(smemraw, blockIdx.x, g_pos1, g_P1, g_Q1, w2, b2, g_x1, R2);
    } else {
        int b = blockIdx.x - CONV1_BLOCKS;       // 0..7
        fps_body<M1, M2, 2>(smemraw, b, g_pos1, g_idx2, g_pos2);
        if (batch_out) {                          // 8 blocks x 512 threads = 4096 = B_*M2
            batch_out[b*512 + threadIdx.x] = (float)b;
        }
    }
}

// ---------------- standalone conv2 ----------------
__global__ void __launch_bounds__(512)
k_conv2(const float* __restrict__ w2, const float* __restrict__ b2,
        float* __restrict__ out, float R2) {
    extern __shared__ char smemraw[];
    conv_body<M2,H2,C2OUT>(smemraw, blockIdx.x, g_pos2, g_P2, g_Q2, w2, b2, out, R2);
}

// ---------------- launch ----------------
extern "C" void kernel_launch(void* const* d_in, const int* in_sizes, int n_in,
                              void* d_out, int out_size) {
    const float *pos, *c1_w1, *c1_b1, *c1_g, *c1_be, *c1_m, *c1_v, *c1_w2, *c1_b2;
    const float *c2_w1, *c2_b1, *c2_g, *c2_be, *c2_m, *c2_v, *c2_w2, *c2_b2;
    if (in_sizes[0] == B_*N_*3) {
        pos   = (const float*)d_in[0];
        c1_w1 = (const float*)d_in[1];  c1_b1 = (const float*)d_in[2];
        c1_g  = (const float*)d_in[3];  c1_be = (const float*)d_in[4];
        c1_m  = (const float*)d_in[5];  c1_v  = (const float*)d_in[6];
        c1_w2 = (const float*)d_in[7];  c1_b2 = (const float*)d_in[8];
        c2_w1 = (const float*)d_in[9];  c2_b1 = (const float*)d_in[10];
        c2_g  = (const float*)d_in[11]; c2_be = (const float*)d_in[12];
        c2_m  = (const float*)d_in[13]; c2_v  = (const float*)d_in[14];
        c2_w2 = (const float*)d_in[15]; c2_b2 = (const float*)d_in[16];
    } else {
        c1_b1 = (const float*)d_in[1];  c1_b2 = (const float*)d_in[2];
        c1_be = (const float*)d_in[3];  c1_g  = (const float*)d_in[4];
        c1_m  = (const float*)d_in[5];  c1_v  = (const float*)d_in[6];
        c1_w1 = (const float*)d_in[7];  c1_w2 = (const float*)d_in[8];
        c2_b1 = (const float*)d_in[9];  c2_b2 = (const float*)d_in[10];
        c2_be = (const float*)d_in[11]; c2_g  = (const float*)d_in[12];
        c2_m  = (const float*)d_in[13]; c2_v  = (const float*)d_in[14];
        c2_w1 = (const float*)d_in[15]; c2_w2 = (const float*)d_in[16];
        pos   = (const float*)d_in[17];
    }
    float* out = (float*)d_out;

    const size_t smem1 = conv_smem_bytes(M1, H1, C1OUT);
    const size_t smem2 = conv_smem_bytes(M2, H2, C2OUT);
    const size_t smemP2 = (64*128 + 128*68) * sizeof(float);
    cudaFuncSetAttribute(k_conv1_fps2, cudaFuncAttributeMaxDynamicSharedMemorySize, (int)smem1);
    cudaFuncSetAttribute(k_conv2,      cudaFuncAttributeMaxDynamicSharedMemorySize, (int)smem2);
    cudaFuncSetAttribute(k_prep2,      cudaFuncAttributeMaxDynamicSharedMemorySize, (int)smemP2);

    float* batch_out = ((size_t)out_size >= (size_t)B_*M2*C2OUT + B_*M2)
                     ? out + (size_t)B_*M2*C2OUT : nullptr;

    k_norm_fps1<<<B_, 512>>>(pos);
    k_prep1<<<(B_*M1*H1 + 255)/256, 256>>>(c1_w1, c1_b1, c1_g, c1_be, c1_m, c1_v);
    {
        float r2 = (float)(0.1 * 0.1);   // matches JAX f32 scalar exactly
        k_conv1_fps2<<<CONV1_BLOCKS + B_, 512, smem1>>>(c1_w2, c1_b2, batch_out, r2);
    }
    k_prep2<<<dim3(B_*M2/64, H2/64), 256, smemP2>>>(c2_w1, c2_b1, c2_g, c2_v);
    k_prep2q<<<(B_*M2*H2 + 255)/256, 256>>>(c2_w1, c2_g, c2_be, c2_m, c2_v);
    {
        float r2 = (float)(0.25 * 0.25);
        k_conv2<<<B_*(M2/QPB), 512, smem2>>>(c2_w2, c2_b2, out, r2);
    }
    (void)in_sizes; (void)n_in;
}

// round 14
// speedup vs baseline: 2.0810x; 1.0639x over previous
#include <cuda_runtime.h>
#include <cuda_bf16.h>
#include <math.h>

// Problem constants
constexpr int B_ = 8, N_ = 2048;
constexpr int M1 = 1024, M2 = 512;
constexpr int H1 = 128, C1OUT = 128;
constexpr int H2 = 256, C2OUT = 512;
constexpr int KMAX = 64;
constexpr int QPB = 32;   // queries per conv block (2 per warp)
constexpr int MT  = 64;   // pair m-tile
constexpr int NT  = 128;  // n-tile
constexpr int KT  = 32;   // k-tile
constexpr int CONV1_BLOCKS = B_*(M1/QPB);   // 256

// ---------------- scratch (__device__ globals; device-code references ONLY) ----------------
__device__ int   g_idx1[B_*M1];
__device__ float g_pos1[B_*M1*3];
__device__ float g_P1  [B_*M1*H1];
__device__ float g_Q1  [B_*M1*H1];
__device__ float g_x1  [B_*M1*C1OUT];
__device__ int   g_idx2[B_*M2];
__device__ float g_pos2[B_*M2*3];
__device__ float g_P2  [B_*M2*H2];
__device__ float g_Q2  [B_*M2*H2];

// ---------------- packed f32x2 helpers (bit-exact per-lane .rn) ----------------
__device__ __forceinline__ unsigned long long pk2(float a, float b){
    unsigned long long r;
    asm("mov.b64 %0, {%1, %2};" : "=l"(r) : "f"(a), "f"(b));
    return r;
}
__device__ __forceinline__ void upk2(unsigned long long v, float& a, float& b){
    asm("mov.b64 {%0, %1}, %2;" : "=f"(a), "=f"(b) : "l"(v));
}
__device__ __forceinline__ unsigned long long add2(unsigned long long a, unsigned long long b){
    unsigned long long r;
    asm("add.rn.f32x2 %0, %1, %2;" : "=l"(r) : "l"(a), "l"(b));
    return r;
}
__device__ __forceinline__ unsigned long long mul2(unsigned long long a, unsigned long long b){
    unsigned long long r;
    asm("mul.rn.f32x2 %0, %1, %2;" : "=l"(r) : "l"(a), "l"(b));
    return r;
}

// ---------------- fused normalize + FPS level 1 ----------------
__global__ void __launch_bounds__(512)
k_norm_fps1(const float* __restrict__ pos) {
    constexpr int NP = N_, KSEL = M1, PT = 4, T = 512, NW = T/32;
    int b = blockIdx.x, t = threadIdx.x;
    int lane = t & 31, w = t >> 5;
    __shared__ float sx[NP], sy[NP], sz[NP];
    __shared__ float s_mean[3], s_den[3];
    __shared__ unsigned wb[2][32];
    __shared__ int wi[2][32];
    __shared__ int s_hist[KSEL];
    const float* p = pos + b*NP*3;

    // normalize: strictly sequential accumulation per coordinate (matches XLA)
    if (t < 3) {
        float s = 0.f;
        for (int i = 0; i < NP; ++i) s = __fadd_rn(s, p[i*3 + t]);
        s_mean[t] = __fdiv_rn(s, (float)NP);
    }
    __syncthreads();
    if (t < 3) {
        float mu = s_mean[t];
        float s = 0.f;
        for (int i = 0; i < NP; ++i) {
            float d = __fsub_rn(p[i*3 + t], mu);
            s = __fadd_rn(s, __fmul_rn(d, d));
        }
        float var = __fdiv_rn(s, (float)(NP - 1));
        s_den[t] = __fadd_rn(__fsqrt_rn(var), 1e-6f);
    }
    __syncthreads();
    float mx = s_mean[0], my = s_mean[1], mz = s_mean[2];
    float dx0 = s_den[0], dy0 = s_den[1], dz0 = s_den[2];

    // pack 2 points (slots 2q, 2q+1 -> indices t+2q*T, t+(2q+1)*T) per register pair
    unsigned long long px2[PT/2], py2[PT/2], pz2[PT/2];
    float dd[PT];
    float xs_[PT], ys_[PT], zs_[PT];
    #pragma unroll
    for (int s=0;s<PT;s++){
        int i = t + s*T;
        float x = __fdiv_rn(__fsub_rn(p[i*3+0], mx), dx0);
        float y = __fdiv_rn(__fsub_rn(p[i*3+1], my), dy0);
        float z = __fdiv_rn(__fsub_rn(p[i*3+2], mz), dz0);
        xs_[s]=x; ys_[s]=y; zs_[s]=z; dd[s]=1e10f;
        sx[i]=x; sy[i]=y; sz[i]=z;
    }
    #pragma unroll
    for (int q=0;q<PT/2;q++){
        px2[q]=pk2(xs_[2*q],xs_[2*q+1]);
        py2[q]=pk2(ys_[2*q],ys_[2*q+1]);
        pz2[q]=pk2(zs_[2*q],zs_[2*q+1]);
    }
    if (t < 32) { wb[0][t]=0u; wb[1][t]=0u; wi[0][t]=0x7fffffff; wi[1][t]=0x7fffffff; }
    if (t==0) s_hist[0] = 0;
    __syncthreads();

    int win = 0;
    for (int it=1; it<KSEL; ++it) {
        // a - b == a + (-b) exactly (IEEE); pre-negate query coords once
        float nlx = -sx[win], nly = -sy[win], nlz = -sz[win];
        unsigned long long nlx2 = pk2(nlx,nlx), nly2 = pk2(nly,nly), nlz2 = pk2(nlz,nlz);
        float bd = -1.f; int bi = 0;
        #pragma unroll
        for (int q=0;q<PT/2;q++){
            unsigned long long dx = add2(px2[q], nlx2);
            unsigned long long dy = add2(py2[q], nly2);
            unsigned long long dz = add2(pz2[q], nlz2);
            unsigned long long d2 = add2(add2(mul2(dx,dx), mul2(dy,dy)), mul2(dz,dz));
            float d0, d1; upk2(d2, d0, d1);
            int s0 = 2*q, s1 = 2*q+1;
            dd[s0] = fminf(dd[s0], d0);
            if (dd[s0] > bd) { bd = dd[s0]; bi = t + s0*T; }
            dd[s1] = fminf(dd[s1], d1);
            if (dd[s1] > bd) { bd = dd[s1]; bi = t + s1*T; }
        }
        unsigned mybits = __float_as_uint(bd);
        unsigned mb = __reduce_max_sync(0xffffffffu, mybits);
        unsigned cand = (mybits == mb) ? (unsigned)bi : 0xffffffffu;
        unsigned mi = __reduce_min_sync(0xffffffffu, cand);
        int par = it & 1;
        if (lane==0){ wb[par][w]=mb; wi[par][w]=(int)mi; }
        __syncthreads();
        unsigned vb = (lane < NW) ? wb[par][lane] : 0u;
        int      vi = (lane < NW) ? wi[par][lane] : 0x7fffffff;
        unsigned mb2 = __reduce_max_sync(0xffffffffu, vb);
        unsigned cand2 = (vb==mb2) ? (unsigned)vi : 0xffffffffu;
        win = (int)__reduce_min_sync(0xffffffffu, cand2);
        if (t==0) s_hist[it] = win;
    }
    __syncthreads();
    for (int i = t; i < KSEL; i += T) {
        int h = s_hist[i];
        g_idx1[b*KSEL+i] = h;
        g_pos1[(b*KSEL+i)*3+0] = sx[h];
        g_pos1[(b*KSEL+i)*3+1] = sy[h];
        g_pos1[(b*KSEL+i)*3+2] = sz[h];
    }
}

// ---------------- FPS body (level 2, smem carved from dynamic) ----------------
template<int NP, int KSEL, int PT>
__device__ __forceinline__ void fps_body(char* smemraw, int b,
                                         const float* __restrict__ src,
                                         int* __restrict__ idx_out,
                                         float* __restrict__ pos_out) {
    constexpr int T = 512, NW = T/32;
    float*    sx = (float*)smemraw;
    float*    sy = sx + NP;
    float*    sz = sy + NP;
    unsigned* wb = (unsigned*)(sz + NP);       // [2][32]
    int*      wi = (int*)(wb + 64);            // [2][32]
    int*  s_hist = wi + 64;                    // [KSEL]

    int t = threadIdx.x, lane = t & 31, w = t >> 5;
    const float* p = src + b*NP*3;

    unsigned long long px2[PT/2], py2[PT/2], pz2[PT/2];
    float dd[PT];
    float xs_[PT], ys_[PT], zs_[PT];
    #pragma unroll
    for (int s=0;s<PT;s++){
        int i = t + s*T;
        float x=p[i*3+0], y=p[i*3+1], z=p[i*3+2];
        xs_[s]=x; ys_[s]=y; zs_[s]=z; dd[s]=1e10f;
        sx[i]=x; sy[i]=y; sz[i]=z;
    }
    #pragma unroll
    for (int q=0;q<PT/2;q++){
        px2[q]=pk2(xs_[2*q],xs_[2*q+1]);
        py2[q]=pk2(ys_[2*q],ys_[2*q+1]);
        pz2[q]=pk2(zs_[2*q],zs_[2*q+1]);
    }
    if (t < 32) { wb[t]=0u; wb[32+t]=0u; wi[t]=0x7fffffff; wi[32+t]=0x7fffffff; }
    if (t==0) s_hist[0] = 0;
    __syncthreads();

    int win = 0;
    for (int it=1; it<KSEL; ++it) {
        float nlx = -sx[win], nly = -sy[win], nlz = -sz[win];
        unsigned long long nlx2 = pk2(nlx,nlx), nly2 = pk2(nly,nly), nlz2 = pk2(nlz,nlz);
        float bd = -1.f; int bi = 0;
        #pragma unroll
        for (int q=0;q<PT/2;q++){
            unsigned long long dx = add2(px2[q], nlx2);
            unsigned long long dy = add2(py2[q], nly2);
            unsigned long long dz = add2(pz2[q], nlz2);
            unsigned long long d2 = add2(add2(mul2(dx,dx), mul2(dy,dy)), mul2(dz,dz));
            float d0, d1; upk2(d2, d0, d1);
            int s0 = 2*q, s1 = 2*q+1;
            dd[s0] = fminf(dd[s0], d0);
            if (dd[s0] > bd) { bd = dd[s0]; bi = t + s0*T; }
            dd[s1] = fminf(dd[s1], d1);
            if (dd[s1] > bd) { bd = dd[s1]; bi = t + s1*T; }
        }
        unsigned mybits = __float_as_uint(bd);
        unsigned mb = __reduce_max_sync(0xffffffffu, mybits);
        unsigned cand = (mybits == mb) ? (unsigned)bi : 0xffffffffu;
        unsigned mi = __reduce_min_sync(0xffffffffu, cand);
        int par = it & 1;
        if (lane==0){ wb[par*32+w]=mb; wi[par*32+w]=(int)mi; }
        __syncthreads();
        unsigned vb = (lane < NW) ? wb[par*32+lane] : 0u;
        int      vi = (lane < NW) ? wi[par*32+lane] : 0x7fffffff;
        unsigned mb2 = __reduce_max_sync(0xffffffffu, vb);
        unsigned cand2 = (vb==mb2) ? (unsigned)vi : 0xffffffffu;
        win = (int)__reduce_min_sync(0xffffffffu, cand2);
        if (t==0) s_hist[it] = win;
    }
    __syncthreads();
    for (int i = t; i < KSEL; i += 512) {
        int h = s_hist[i];
        idx_out[b*KSEL+i] = h;
        pos_out[(b*KSEL+i)*3+0] = sx[h];
        pos_out[(b*KSEL+i)*3+1] = sy[h];
        pos_out[(b*KSEL+i)*3+2] = sz[h];
    }
}

// ---------------- level-1 P/Q precompute (BN folded) ----------------
__global__ void k_prep1(const float* __restrict__ w1, const float* __restrict__ b1,
                        const float* __restrict__ g, const float* __restrict__ beta,
                        const float* __restrict__ m, const float* __restrict__ v) {
    int idx = blockIdx.x*256 + threadIdx.x;
    if (idx >= B_*M1*H1) return;
    int c = idx & (H1-1), pj = idx >> 7;
    float x = g_pos1[pj*3+0], y = g_pos1[pj*3+1], z = g_pos1[pj*3+2];
    float s = g[c] / sqrtf(v[c] + 1e-5f);
    float t = beta[c] - m[c]*s;
    float wa0=w1[0*H1+c], wa1=w1[1*H1+c], wa2=w1[2*H1+c];
    float wb0=w1[3*H1+c], wb1=w1[4*H1+c], wb2=w1[5*H1+c];
    float A = x*(wa0+wb0) + y*(wa1+wb1) + z*(wa2+wb2) + b1[c];
    g_P1[idx] = A * s;
    float q = -(x*wb0 + y*wb1 + z*wb2);
    g_Q1[idx] = q * s + t;
}

// ---------------- level-2 P precompute: gathered GEMM [4096,128]@[128,256] ----------------
__global__ void k_prep2(const float* __restrict__ w1, const float* __restrict__ b1,
                        const float* __restrict__ g, const float* __restrict__ v) {
    extern __shared__ char smemraw[];
    float* xs = (float*)smemraw;            // [64][128]
    float* ws = xs + 64*128;                // [128][68] padded
    int tid = threadIdx.x;                  // 256
    int row0 = blockIdx.x * 64;
    int n0   = blockIdx.y * 64;
    int b = row0 / M2;

    for (int i = tid; i < 64*128; i += 256) {
        int r = i >> 7, k = i & 127;
        int jj = g_idx2[row0 + r];
        xs[r*128 + k] = g_x1[(b*M1 + jj)*H1 + k];
    }
    for (int i = tid; i < 128*64; i += 256) {
        int k = i >> 6, nn = i & 63;
        ws[k*68 + nn] = w1[k*H2 + n0 + nn];
    }
    __syncthreads();

    int ty = tid >> 4, tx = tid & 15;
    float acc[4][4] = {};
    #pragma unroll 4
    for (int k = 0; k < 128; ++k) {
        float a0 = xs[(ty*4+0)*128 + k];
        float a1 = xs[(ty*4+1)*128 + k];
        float a2 = xs[(ty*4+2)*128 + k];
        float a3 = xs[(ty*4+3)*128 + k];
        float4 bv = *(const float4*)&ws[k*68 + tx*4];
        acc[0][0]+=a0*bv.x; acc[0][1]+=a0*bv.y; acc[0][2]+=a0*bv.z; acc[0][3]+=a0*bv.w;
        acc[1][0]+=a1*bv.x; acc[1][1]+=a1*bv.y; acc[1][2]+=a1*bv.z; acc[1][3]+=a1*bv.w;
        acc[2][0]+=a2*bv.x; acc[2][1]+=a2*bv.y; acc[2][2]+=a2*bv.z; acc[2][3]+=a2*bv.w;
        acc[3][0]+=a3*bv.x; acc[3][1]+=a3*bv.y; acc[3][2]+=a3*bv.z; acc[3][3]+=a3*bv.w;
    }
    #pragma unroll
    for (int mi=0; mi<4; ++mi) {
        int r = row0 + ty*4 + mi;
        float px = g_pos2[r*3+0], py = g_pos2[r*3+1], pz = g_pos2[r*3+2];
        #pragma unroll
        for (int ni=0; ni<4; ++ni) {
            int n = n0 + tx*4 + ni;
            float s = g[n] / sqrtf(v[n] + 1e-5f);
            float A = acc[mi][ni]
                    + px*w1[128*H2 + n] + py*w1[129*H2 + n] + pz*w1[130*H2 + n] + b1[n];
            g_P2[r*H2 + n] = A * s;
        }
    }
}

__global__ void k_prep2q(const float* __restrict__ w1, const float* __restrict__ g,
                         const float* __restrict__ beta, const float* __restrict__ m,
                         const float* __restrict__ v) {
    int idx = blockIdx.x*256 + threadIdx.x;
    if (idx >= B_*M2*H2) return;
    int c = idx & (H2-1), pj = idx >> 8;
    float x = g_pos2[pj*3+0], y = g_pos2[pj*3+1], z = g_pos2[pj*3+2];
    float s = g[c] / sqrtf(v[c] + 1e-5f);
    float t = beta[c] - m[c]*s;
    float q = -(x*w1[128*H2+c] + y*w1[129*H2+c] + z*w1[130*H2+c]);
    g_Q2[idx] = q * s + t;
}

// ---------------- ball-query + pair-list GEMM + max aggregation (device body) ----------------
constexpr size_t conv_smem_bytes(int MSRC, int HDIM, int COUT) {
    return (size_t)(MSRC*3 + QPB*KMAX + QPB*KMAX + QPB + QPB*KMAX + QPB*KMAX + 64
                    + MT*HDIM + KT*(NT+4) + QPB*COUT) * 4;
}

template<int MSRC, int HDIM, int COUT>
__device__ __forceinline__ void conv_body(char* smemraw, int blk,
        const float* __restrict__ srcpos, const float* __restrict__ P,
        const float* __restrict__ Q, const float* __restrict__ w2,
        const float* __restrict__ b2, float* __restrict__ out, float R2) {
    float*    s_pos = (float*)smemraw;                 // MSRC*3
    float*    s_pd  = s_pos + MSRC*3;                  // QPB*KMAX
    int*      s_pj  = (int*)(s_pd + QPB*KMAX);         // QPB*KMAX
    int*      s_cnt = s_pj + QPB*KMAX;                 // QPB
    int*      s_fi  = s_cnt + QPB;                     // QPB*KMAX
    int*      s_fj  = s_fi + QPB*KMAX;                 // QPB*KMAX
    int*      s_qoff= s_fj + QPB*KMAX;                 // 64
    float*    s_h   = (float*)(s_qoff + 64);           // MT*HDIM
    float*    s_w   = s_h + MT*HDIM;                   // KT*(NT+4)
    unsigned* s_out = (unsigned*)(s_w + KT*(NT+4));    // QPB*COUT

    int b  = blk / (MSRC/QPB);
    int q0 = (blk % (MSRC/QPB)) * QPB;
    int tid = threadIdx.x, lane = tid & 31, w = tid >> 5;

    for (int i = tid; i < MSRC*3; i += 512) s_pos[i] = srcpos[b*MSRC*3 + i];
    __syncthreads();

    for (int qq = 0; qq < 2; ++qq) {
        int qslot = w*2 + qq;
        int qi = q0 + qslot;
        float qx = s_pos[qi*3+0], qy = s_pos[qi*3+1], qz = s_pos[qi*3+2];
        int cnt = 0;
        for (int base = 0; base < MSRC; base += 32) {
            int j = base + lane;
            float dx = __fsub_rn(s_pos[j*3+0], qx);
            float dy = __fsub_rn(s_pos[j*3+1], qy);
            float dz = __fsub_rn(s_pos[j*3+2], qz);
            float d2 = __fadd_rn(__fadd_rn(__fmul_rn(dx,dx),__fmul_rn(dy,dy)),__fmul_rn(dz,dz));
            bool pred = (d2 <= R2);
            unsigned ball = __ballot_sync(0xffffffffu, pred);
            int nb = __popc(ball);
            if (cnt + nb <= KMAX) {
                if (pred) {
                    int pos = cnt + __popc(ball & ((1u<<lane)-1u));
                    s_pj[qslot*KMAX+pos] = j; s_pd[qslot*KMAX+pos] = d2;
                }
                cnt += nb;
            } else {
                unsigned rem = ball;
                while (rem) {
                    int l = __ffs(rem)-1; rem &= rem-1u;
                    float cd2 = __shfl_sync(0xffffffffu, d2, l);
                    int cj = base + l;
                    if (cnt < KMAX) {
                        if (lane==0){ s_pj[qslot*KMAX+cnt]=cj; s_pd[qslot*KMAX+cnt]=cd2; }
                        cnt++;
                    } else {
                        float e0 = s_pd[qslot*KMAX+lane],    e1 = s_pd[qslot*KMAX+32+lane];
                        int   j0 = s_pj[qslot*KMAX+lane],    j1 = s_pj[qslot*KMAX+32+lane];
                        float md; int ms, mj;
                        if (e1 > e0 || (e1==e0 && j1>j0)) { md=e1; ms=32+lane; mj=j1; }
                        else                               { md=e0; ms=lane;    mj=j0; }
                        #pragma unroll
                        for (int o=16;o;o>>=1){
                            float od = __shfl_xor_sync(~0u, md, o);
                            int   os = __shfl_xor_sync(~0u, ms, o);
                            int   oj = __shfl_xor_sync(~0u, mj, o);
                            if (od > md || (od==md && oj>mj)) { md=od; ms=os; mj=oj; }
                        }
                        if (cd2 < md) {
                            if (lane==0){ s_pj[qslot*KMAX+ms]=cj; s_pd[qslot*KMAX+ms]=cd2; }
                        }
                    }
                    __syncwarp();
                }
            }
        }
        if (lane==0) s_cnt[qslot] = cnt;
    }
    __syncthreads();

    if (tid==0){
        int acc=0;
        for (int i=0;i<QPB;i++){ s_qoff[i]=acc; acc+=s_cnt[i]; }
        s_qoff[QPB]=acc;
    }
    __syncthreads();
    for (int qq = 0; qq < 2; ++qq) {
        int qslot = w*2 + qq;
        int off = s_qoff[qslot], c = s_cnt[qslot];
        for (int e = lane; e < c; e += 32){ s_fi[off+e]=qslot; s_fj[off+e]=s_pj[qslot*KMAX+e]; }
    }
    for (int i = tid; i < QPB*COUT; i += 512) s_out[i] = 0u;
    __syncthreads();

    int total = s_qoff[QPB];
    int ty = tid >> 5, tx = tid & 31;

    for (int m0 = 0; m0 < total; m0 += MT) {
        for (int i = tid; i < MT*HDIM; i += 512) {
            int mp = i / HDIM, k = i % HDIM;
            float val = 0.f;
            if (m0 + mp < total) {
                int qi = s_fi[m0+mp], j = s_fj[m0+mp];
                val = fmaxf(P[(size_t)(b*MSRC + j)*HDIM + k] + Q[(size_t)(b*MSRC + q0 + qi)*HDIM + k], 0.f);
            }
            s_h[i] = val;
        }
        __syncthreads();

        for (int n0 = 0; n0 < COUT; n0 += NT) {
            float acc[4][4] = {};
            for (int k0 = 0; k0 < HDIM; k0 += KT) {
                for (int i = tid; i < KT*NT; i += 512) {
                    int kk = i / NT, nn = i % NT;
                    s_w[kk*(NT+4)+nn] = w2[(size_t)(k0+kk)*COUT + n0 + nn];
                }
                __syncthreads();
                #pragma unroll
                for (int kk = 0; kk < KT; ++kk) {
                    float a0 = s_h[(ty*4+0)*HDIM + k0+kk];
                    float a1 = s_h[(ty*4+1)*HDIM + k0+kk];
                    float a2 = s_h[(ty*4+2)*HDIM + k0+kk];
                    float a3 = s_h[(ty*4+3)*HDIM + k0+kk];
                    float4 bv = *(const float4*)&s_w[kk*(NT+4) + tx*4];
                    acc[0][0]+=a0*bv.x; acc[0][1]+=a0*bv.y; acc[0][2]+=a0*bv.z; acc[0][3]+=a0*bv.w;
                    acc[1][0]+=a1*bv.x; acc[1][1]+=a1*bv.y; acc[1][2]+=a1*bv.z; acc[1][3]+=a1*bv.w;
                    acc[2][0]+=a2*bv.x; acc[2][1]+=a2*bv.y; acc[2][2]+=a2*bv.z; acc[2][3]+=a2*bv.w;
                    acc[3][0]+=a3*bv.x; acc[3][1]+=a3*bv.y; acc[3][2]+=a3*bv.z; acc[3][3]+=a3*bv.w;
                }
                __syncthreads();
            }
            #pragma unroll
            for (int mi=0; mi<4; ++mi) {
                int mp = ty*4 + mi;
                if (m0 + mp < total) {
                    int qi = s_fi[m0+mp];
                    #pragma unroll
                    for (int ni=0; ni<4; ++ni) {
                        int n = n0 + tx*4 + ni;
                        float val = fmaxf(acc[mi][ni] + b2[n], 0.f);
                        atomicMax(&s_out[qi*COUT + n], __float_as_uint(val));
                    }
                }
            }
            __syncthreads();
        }
    }

    for (int i = tid; i < QPB*COUT; i += 512) {
        int q = i / COUT, c = i % COUT;
        out[(size_t)(b*MSRC + q0 + q)*COUT + c] = __uint_as_float(s_out[i]);
    }
}

// ---------------- fused conv1 + fps2 + batch2 (single-kernel overlap) ----------------
__global__ void __launch_bounds__(512)
k_conv1_fps2(const float* __restrict__ w2, const float* __restrict__ b2,
             float* __restrict__ batch_out, float R2) {
    extern __shared__ char smemraw[];
    if (blockIdx.x < CONV1_BLOCKS) {
        conv_body<M1,H1,C1OUT>(smemraw, blockIdx.x, g_pos1, g_P1, g_Q1, w2, b2, g_x1, R2);
    } else {
        int b = blockIdx.x - CONV1_BLOCKS;       // 0..7
        fps_body<M1, M2, 2>(smemraw, b, g_pos1, g_idx2, g_pos2);
        if (batch_out) {                          // 8 blocks x 512 threads = 4096 = B_*M2
            batch_out[b*512 + threadIdx.x] = (float)b;
        }
    }
}

// ---------------- standalone conv2 ----------------
__global__ void __launch_bounds__(512)
k_conv2(const float* __restrict__ w2, const float* __restrict__ b2,
        float* __restrict__ out, float R2) {
    extern __shared__ char smemraw[];
    conv_body<M2,H2,C2OUT>(smemraw, blockIdx.x, g_pos2, g_P2, g_Q2, w2, b2, out, R2);
}

// ---------------- launch ----------------
extern "C" void kernel_launch(void* const* d_in, const int* in_sizes, int n_in,
                              void* d_out, int out_size) {
    const float *pos, *c1_w1, *c1_b1, *c1_g, *c1_be, *c1_m, *c1_v, *c1_w2, *c1_b2;
    const float *c2_w1, *c2_b1, *c2_g, *c2_be, *c2_m, *c2_v, *c2_w2, *c2_b2;
    if (in_sizes[0] == B_*N_*3) {
        pos   = (const float*)d_in[0];
        c1_w1 = (const float*)d_in[1];  c1_b1 = (const float*)d_in[2];
        c1_g  = (const float*)d_in[3];  c1_be = (const float*)d_in[4];
        c1_m  = (const float*)d_in[5];  c1_v  = (const float*)d_in[6];
        c1_w2 = (const float*)d_in[7];  c1_b2 = (const float*)d_in[8];
        c2_w1 = (const float*)d_in[9];  c2_b1 = (const float*)d_in[10];
        c2_g  = (const float*)d_in[11]; c2_be = (const float*)d_in[12];
        c2_m  = (const float*)d_in[13]; c2_v  = (const float*)d_in[14];
        c2_w2 = (const float*)d_in[15]; c2_b2 = (const float*)d_in[16];
    } else {
        c1_b1 = (const float*)d_in[1];  c1_b2 = (const float*)d_in[2];
        c1_be = (const float*)d_in[3];  c1_g  = (const float*)d_in[4];
        c1_m  = (const float*)d_in[5];  c1_v  = (const float*)d_in[6];
        c1_w1 = (const float*)d_in[7];  c1_w2 = (const float*)d_in[8];
        c2_b1 = (const float*)d_in[9];  c2_b2 = (const float*)d_in[10];
        c2_be = (const float*)d_in[11]; c2_g  = (const float*)d_in[12];
        c2_m  = (const float*)d_in[13]; c2_v  = (const float*)d_in[14];
        c2_w1 = (const float*)d_in[15]; c2_w2 = (const float*)d_in[16];
        pos   = (const float*)d_in[17];
    }
    float* out = (float*)d_out;

    const size_t smem1 = conv_smem_bytes(M1, H1, C1OUT);
    const size_t smem2 = conv_smem_bytes(M2, H2, C2OUT);
    const size_t smemP2 = (64*128 + 128*68) * sizeof(float);
    cudaFuncSetAttribute(k_conv1_fps2, cudaFuncAttributeMaxDynamicSharedMemorySize, (int)smem1);
    cudaFuncSetAttribute(k_conv2,      cudaFuncAttributeMaxDynamicSharedMemorySize, (int)smem2);
    cudaFuncSetAttribute(k_prep2,      cudaFuncAttributeMaxDynamicSharedMemorySize, (int)smemP2);

    float* batch_out = ((size_t)out_size >= (size_t)B_*M2*C2OUT + B_*M2)
                     ? out + (size_t)B_*M2*C2OUT : nullptr;

    k_norm_fps1<<<B_, 512>>>(pos);
    k_prep1<<<(B_*M1*H1 + 255)/256, 256>>>(c1_w1, c1_b1, c1_g, c1_be, c1_m, c1_v);
    {
        float r2 = (float)(0.1 * 0.1);   // matches JAX f32 scalar exactly
        k_conv1_fps2<<<CONV1_BLOCKS + B_, 512, smem1>>>(c1_w2, c1_b2, batch_out, r2);
    }
    k_prep2<<<dim3(B_*M2/64, H2/64), 256, smemP2>>>(c2_w1, c2_b1, c2_g, c2_v);
    k_prep2q<<<(B_*M2*H2 + 255)/256, 256>>>(c2_w1, c2_g, c2_be, c2_m, c2_v);
    {
        float r2 = (float)(0.25 * 0.25);
        k_conv2<<<B_*(M2/QPB), 512, smem2>>>(c2_w2, c2_b2, out, r2);
    }
    (void)in_sizes; (void)n_in;
}

// round 15
// speedup vs baseline: 2.1536x; 1.0349x over previous
#include <cuda_runtime.h>
#include <cuda_bf16.h>
#include <math.h>

// Problem constants
constexpr int B_ = 8, N_ = 2048;
constexpr int M1 = 1024, M2 = 512;
constexpr int H1 = 128, C1OUT = 128;
constexpr int H2 = 256, C2OUT = 512;
constexpr int KMAX = 64;
constexpr int QPB = 32;   // queries per conv block (2 per warp)
constexpr int MT  = 64;   // pair m-tile
constexpr int NT  = 128;  // n-tile
constexpr int KT  = 32;   // k-tile
constexpr int CONV1_BLOCKS = B_*(M1/QPB);   // 256

// ---------------- scratch (__device__ globals; device-code references ONLY) ----------------
__device__ int   g_idx1[B_*M1];
__device__ float g_pos1[B_*M1*3];
__device__ float g_P1  [B_*M1*H1];
__device__ float g_Q1  [B_*M1*H1];
__device__ float g_x1  [B_*M1*C1OUT];
__device__ int   g_idx2[B_*M2];
__device__ float g_pos2[B_*M2*3];
__device__ float g_P2  [B_*M2*H2];
__device__ float g_Q2  [B_*M2*H2];

// ---------------- packed f32x2 helpers (bit-exact per-lane .rn) ----------------
__device__ __forceinline__ unsigned long long pk2(float a, float b){
    unsigned long long r;
    asm("mov.b64 %0, {%1, %2};" : "=l"(r) : "f"(a), "f"(b));
    return r;
}
__device__ __forceinline__ void upk2(unsigned long long v, float& a, float& b){
    asm("mov.b64 {%0, %1}, %2;" : "=f"(a), "=f"(b) : "l"(v));
}
__device__ __forceinline__ unsigned long long add2(unsigned long long a, unsigned long long b){
    unsigned long long r;
    asm("add.rn.f32x2 %0, %1, %2;" : "=l"(r) : "l"(a), "l"(b));
    return r;
}
__device__ __forceinline__ unsigned long long mul2(unsigned long long a, unsigned long long b){
    unsigned long long r;
    asm("mul.rn.f32x2 %0, %1, %2;" : "=l"(r) : "l"(a), "l"(b));
    return r;
}

// ---------------- fused normalize + FPS level 1 ----------------
__global__ void __launch_bounds__(512)
k_norm_fps1(const float* __restrict__ pos) {
    constexpr int NP = N_, KSEL = M1, PT = 4, T = 512, NW = T/32;
    int b = blockIdx.x, t = threadIdx.x;
    int lane = t & 31, w = t >> 5;
    __shared__ float sx[NP], sy[NP], sz[NP];
    __shared__ float s_mean[3], s_den[3];
    __shared__ unsigned wb[2][32];
    __shared__ int wi[2][32];
    __shared__ int s_hist[KSEL];
    const float* p = pos + b*NP*3;

    // normalize: strictly sequential accumulation per coordinate (matches XLA)
    if (t < 3) {
        float s = 0.f;
        for (int i = 0; i < NP; ++i) s = __fadd_rn(s, p[i*3 + t]);
        s_mean[t] = __fdiv_rn(s, (float)NP);
    }
    __syncthreads();
    if (t < 3) {
        float mu = s_mean[t];
        float s = 0.f;
        for (int i = 0; i < NP; ++i) {
            float d = __fsub_rn(p[i*3 + t], mu);
            s = __fadd_rn(s, __fmul_rn(d, d));
        }
        float var = __fdiv_rn(s, (float)(NP - 1));
        s_den[t] = __fadd_rn(__fsqrt_rn(var), 1e-6f);
    }
    __syncthreads();
    float mx = s_mean[0], my = s_mean[1], mz = s_mean[2];
    float dx0 = s_den[0], dy0 = s_den[1], dz0 = s_den[2];

    unsigned long long px2[PT/2], py2[PT/2], pz2[PT/2];
    float dd[PT];
    float xs_[PT], ys_[PT], zs_[PT];
    #pragma unroll
    for (int s=0;s<PT;s++){
        int i = t + s*T;
        float x = __fdiv_rn(__fsub_rn(p[i*3+0], mx), dx0);
        float y = __fdiv_rn(__fsub_rn(p[i*3+1], my), dy0);
        float z = __fdiv_rn(__fsub_rn(p[i*3+2], mz), dz0);
        xs_[s]=x; ys_[s]=y; zs_[s]=z; dd[s]=1e10f;
        sx[i]=x; sy[i]=y; sz[i]=z;
    }
    #pragma unroll
    for (int q=0;q<PT/2;q++){
        px2[q]=pk2(xs_[2*q],xs_[2*q+1]);
        py2[q]=pk2(ys_[2*q],ys_[2*q+1]);
        pz2[q]=pk2(zs_[2*q],zs_[2*q+1]);
    }
    if (t < 32) { wb[0][t]=0u; wb[1][t]=0u; wi[0][t]=0x7fffffff; wi[1][t]=0x7fffffff; }
    if (t==0) s_hist[0] = 0;
    __syncthreads();

    int win = 0;
    for (int it=1; it<KSEL; ++it) {
        float nlx = -sx[win], nly = -sy[win], nlz = -sz[win];
        unsigned long long nlx2 = pk2(nlx,nlx), nly2 = pk2(nly,nly), nlz2 = pk2(nlz,nlz);
        float bd = -1.f;
        #pragma unroll
        for (int q=0;q<PT/2;q++){
            unsigned long long dx = add2(px2[q], nlx2);
            unsigned long long dy = add2(py2[q], nly2);
            unsigned long long dz = add2(pz2[q], nlz2);
            unsigned long long d2 = add2(add2(mul2(dx,dx), mul2(dy,dy)), mul2(dz,dz));
            float d0, d1; upk2(d2, d0, d1);
            dd[2*q]   = fminf(dd[2*q],   d0);  bd = fmaxf(bd, dd[2*q]);
            dd[2*q+1] = fminf(dd[2*q+1], d1);  bd = fmaxf(bd, dd[2*q+1]);
        }
        // resolve argmax once: lowest s with dd[s]==bd (descending scan)
        int bi = t + (PT-1)*T;
        #pragma unroll
        for (int s=PT-2;s>=0;--s) if (dd[s] == bd) bi = t + s*T;
        unsigned mybits = __float_as_uint(bd);
        unsigned mb = __reduce_max_sync(0xffffffffu, mybits);
        unsigned cand = (mybits == mb) ? (unsigned)bi : 0xffffffffu;
        unsigned mi = __reduce_min_sync(0xffffffffu, cand);
        int par = it & 1;
        if (lane==0){ wb[par][w]=mb; wi[par][w]=(int)mi; }
        __syncthreads();
        unsigned vb = (lane < NW) ? wb[par][lane] : 0u;
        int      vi = (lane < NW) ? wi[par][lane] : 0x7fffffff;
        unsigned mb2 = __reduce_max_sync(0xffffffffu, vb);
        unsigned cand2 = (vb==mb2) ? (unsigned)vi : 0xffffffffu;
        win = (int)__reduce_min_sync(0xffffffffu, cand2);
        if (t==0) s_hist[it] = win;
    }
    __syncthreads();
    for (int i = t; i < KSEL; i += T) {
        int h = s_hist[i];
        g_idx1[b*KSEL+i] = h;
        g_pos1[(b*KSEL+i)*3+0] = sx[h];
        g_pos1[(b*KSEL+i)*3+1] = sy[h];
        g_pos1[(b*KSEL+i)*3+2] = sz[h];
    }
}

// ---------------- FPS body (level 2, smem carved from dynamic) ----------------
template<int NP, int KSEL, int PT>
__device__ __forceinline__ void fps_body(char* smemraw, int b,
                                         const float* __restrict__ src,
                                         int* __restrict__ idx_out,
                                         float* __restrict__ pos_out) {
    constexpr int T = 512, NW = T/32;
    float*    sx = (float*)smemraw;
    float*    sy = sx + NP;
    float*    sz = sy + NP;
    unsigned* wb = (unsigned*)(sz + NP);       // [2][32]
    int*      wi = (int*)(wb + 64);            // [2][32]
    int*  s_hist = wi + 64;                    // [KSEL]

    int t = threadIdx.x, lane = t & 31, w = t >> 5;
    const float* p = src + b*NP*3;

    unsigned long long px2[PT/2], py2[PT/2], pz2[PT/2];
    float dd[PT];
    float xs_[PT], ys_[PT], zs_[PT];
    #pragma unroll
    for (int s=0;s<PT;s++){
        int i = t + s*T;
        float x=p[i*3+0], y=p[i*3+1], z=p[i*3+2];
        xs_[s]=x; ys_[s]=y; zs_[s]=z; dd[s]=1e10f;
        sx[i]=x; sy[i]=y; sz[i]=z;
    }
    #pragma unroll
    for (int q=0;q<PT/2;q++){
        px2[q]=pk2(xs_[2*q],xs_[2*q+1]);
        py2[q]=pk2(ys_[2*q],ys_[2*q+1]);
        pz2[q]=pk2(zs_[2*q],zs_[2*q+1]);
    }
    if (t < 32) { wb[t]=0u; wb[32+t]=0u; wi[t]=0x7fffffff; wi[32+t]=0x7fffffff; }
    if (t==0) s_hist[0] = 0;
    __syncthreads();

    int win = 0;
    for (int it=1; it<KSEL; ++it) {
        float nlx = -sx[win], nly = -sy[win], nlz = -sz[win];
        unsigned long long nlx2 = pk2(nlx,nlx), nly2 = pk2(nly,nly), nlz2 = pk2(nlz,nlz);
        float bd = -1.f;
        #pragma unroll
        for (int q=0;q<PT/2;q++){
            unsigned long long dx = add2(px2[q], nlx2);
            unsigned long long dy = add2(py2[q], nly2);
            unsigned long long dz = add2(pz2[q], nlz2);
            unsigned long long d2 = add2(add2(mul2(dx,dx), mul2(dy,dy)), mul2(dz,dz));
            float d0, d1; upk2(d2, d0, d1);
            dd[2*q]   = fminf(dd[2*q],   d0);  bd = fmaxf(bd, dd[2*q]);
            dd[2*q+1] = fminf(dd[2*q+1], d1);  bd = fmaxf(bd, dd[2*q+1]);
        }
        int bi = t + (PT-1)*T;
        #pragma unroll
        for (int s=PT-2;s>=0;--s) if (dd[s] == bd) bi = t + s*T;
        unsigned mybits = __float_as_uint(bd);
        unsigned mb = __reduce_max_sync(0xffffffffu, mybits);
        unsigned cand = (mybits == mb) ? (unsigned)bi : 0xffffffffu;
        unsigned mi = __reduce_min_sync(0xffffffffu, cand);
        int par = it & 1;
        if (lane==0){ wb[par*32+w]=mb; wi[par*32+w]=(int)mi; }
        __syncthreads();
        unsigned vb = (lane < NW) ? wb[par*32+lane] : 0u;
        int      vi = (lane < NW) ? wi[par*32+lane] : 0x7fffffff;
        unsigned mb2 = __reduce_max_sync(0xffffffffu, vb);
        unsigned cand2 = (vb==mb2) ? (unsigned)vi : 0xffffffffu;
        win = (int)__reduce_min_sync(0xffffffffu, cand2);
        if (t==0) s_hist[it] = win;
    }
    __syncthreads();
    for (int i = t; i < KSEL; i += 512) {
        int h = s_hist[i];
        idx_out[b*KSEL+i] = h;
        pos_out[(b*KSEL+i)*3+0] = sx[h];
        pos_out[(b*KSEL+i)*3+1] = sy[h];
        pos_out[(b*KSEL+i)*3+2] = sz[h];
    }
}

// ---------------- level-1 P/Q precompute (BN folded) ----------------
__global__ void k_prep1(const float* __restrict__ w1, const float* __restrict__ b1,
                        const float* __restrict__ g, const float* __restrict__ beta,
                        const float* __restrict__ m, const float* __restrict__ v) {
    int idx = blockIdx.x*256 + threadIdx.x;
    if (idx >= B_*M1*H1) return;
    int c = idx & (H1-1), pj = idx >> 7;
    float x = g_pos1[pj*3+0], y = g_pos1[pj*3+1], z = g_pos1[pj*3+2];
    float s = g[c] / sqrtf(v[c] + 1e-5f);
    float t = beta[c] - m[c]*s;
    float wa0=w1[0*H1+c], wa1=w1[1*H1+c], wa2=w1[2*H1+c];
    float wb0=w1[3*H1+c], wb1=w1[4*H1+c], wb2=w1[5*H1+c];
    float A = x*(wa0+wb0) + y*(wa1+wb1) + z*(wa2+wb2) + b1[c];
    g_P1[idx] = A * s;
    float q = -(x*wb0 + y*wb1 + z*wb2);
    g_Q1[idx] = q * s + t;
}

// ---------------- level-2 P AND Q precompute (fused): gathered GEMM + affine ----------------
__global__ void k_prep2(const float* __restrict__ w1, const float* __restrict__ b1,
                        const float* __restrict__ g, const float* __restrict__ beta,
                        const float* __restrict__ m, const float* __restrict__ v) {
    extern __shared__ char smemraw[];
    float* xs = (float*)smemraw;            // [64][128]
    float* ws = xs + 64*128;                // [128][68] padded
    int tid = threadIdx.x;                  // 256
    int row0 = blockIdx.x * 64;
    int n0   = blockIdx.y * 64;
    int b = row0 / M2;

    for (int i = tid; i < 64*128; i += 256) {
        int r = i >> 7, k = i & 127;
        int jj = g_idx2[row0 + r];
        xs[r*128 + k] = g_x1[(b*M1 + jj)*H1 + k];
    }
    for (int i = tid; i < 128*64; i += 256) {
        int k = i >> 6, nn = i & 63;
        ws[k*68 + nn] = w1[k*H2 + n0 + nn];
    }
    __syncthreads();

    int ty = tid >> 4, tx = tid & 15;
    float acc[4][4] = {};
    #pragma unroll 4
    for (int k = 0; k < 128; ++k) {
        float a0 = xs[(ty*4+0)*128 + k];
        float a1 = xs[(ty*4+1)*128 + k];
        float a2 = xs[(ty*4+2)*128 + k];
        float a3 = xs[(ty*4+3)*128 + k];
        float4 bv = *(const float4*)&ws[k*68 + tx*4];
        acc[0][0]+=a0*bv.x; acc[0][1]+=a0*bv.y; acc[0][2]+=a0*bv.z; acc[0][3]+=a0*bv.w;
        acc[1][0]+=a1*bv.x; acc[1][1]+=a1*bv.y; acc[1][2]+=a1*bv.z; acc[1][3]+=a1*bv.w;
        acc[2][0]+=a2*bv.x; acc[2][1]+=a2*bv.y; acc[2][2]+=a2*bv.z; acc[2][3]+=a2*bv.w;
        acc[3][0]+=a3*bv.x; acc[3][1]+=a3*bv.y; acc[3][2]+=a3*bv.z; acc[3][3]+=a3*bv.w;
    }
    #pragma unroll
    for (int mi=0; mi<4; ++mi) {
        int r = row0 + ty*4 + mi;
        float px = g_pos2[r*3+0], py = g_pos2[r*3+1], pz = g_pos2[r*3+2];
        #pragma unroll
        for (int ni=0; ni<4; ++ni) {
            int n = n0 + tx*4 + ni;
            float s = g[n] / sqrtf(v[n] + 1e-5f);
            float wpx = w1[128*H2 + n], wpy = w1[129*H2 + n], wpz = w1[130*H2 + n];
            float dot = px*wpx + py*wpy + pz*wpz;
            g_P2[r*H2 + n] = (acc[mi][ni] + dot + b1[n]) * s;
            g_Q2[r*H2 + n] = -dot * s + (beta[n] - m[n]*s);
        }
    }
}

// ---------------- ball-query + pair-list GEMM + max aggregation (device body) ----------------
constexpr size_t conv_smem_bytes(int MSRC, int HDIM, int COUT) {
    return (size_t)(MSRC*3 + QPB*KMAX + QPB*KMAX + QPB + QPB*KMAX + QPB*KMAX + 64
                    + MT*HDIM + KT*(NT+4) + QPB*COUT) * 4;
}

template<int MSRC, int HDIM, int COUT>
__device__ __forceinline__ void conv_body(char* smemraw, int blk,
        const float* __restrict__ srcpos, const float* __restrict__ P,
        const float* __restrict__ Q, const float* __restrict__ w2,
        const float* __restrict__ b2, float* __restrict__ out, float R2) {
    float*    s_pos = (float*)smemraw;                 // MSRC*3
    float*    s_pd  = s_pos + MSRC*3;                  // QPB*KMAX
    int*      s_pj  = (int*)(s_pd + QPB*KMAX);         // QPB*KMAX
    int*      s_cnt = s_pj + QPB*KMAX;                 // QPB
    int*      s_fi  = s_cnt + QPB;                     // QPB*KMAX
    int*      s_fj  = s_fi + QPB*KMAX;                 // QPB*KMAX
    int*      s_qoff= s_fj + QPB*KMAX;                 // 64
    float*    s_h   = (float*)(s_qoff + 64);           // MT*HDIM
    float*    s_w   = s_h + MT*HDIM;                   // KT*(NT+4)
    unsigned* s_out = (unsigned*)(s_w + KT*(NT+4));    // QPB*COUT

    int b  = blk / (MSRC/QPB);
    int q0 = (blk % (MSRC/QPB)) * QPB;
    int tid = threadIdx.x, lane = tid & 31, w = tid >> 5;

    for (int i = tid; i < MSRC*3; i += 512) s_pos[i] = srcpos[b*MSRC*3 + i];
    __syncthreads();

    for (int qq = 0; qq < 2; ++qq) {
        int qslot = w*2 + qq;
        int qi = q0 + qslot;
        float qx = s_pos[qi*3+0], qy = s_pos[qi*3+1], qz = s_pos[qi*3+2];
        int cnt = 0;
        for (int base = 0; base < MSRC; base += 32) {
            int j = base + lane;
            float dx = __fsub_rn(s_pos[j*3+0], qx);
            float dy = __fsub_rn(s_pos[j*3+1], qy);
            float dz = __fsub_rn(s_pos[j*3+2], qz);
            float d2 = __fadd_rn(__fadd_rn(__fmul_rn(dx,dx),__fmul_rn(dy,dy)),__fmul_rn(dz,dz));
            bool pred = (d2 <= R2);
            unsigned ball = __ballot_sync(0xffffffffu, pred);
            int nb = __popc(ball);
            if (cnt + nb <= KMAX) {
                if (pred) {
                    int pos = cnt + __popc(ball & ((1u<<lane)-1u));
                    s_pj[qslot*KMAX+pos] = j; s_pd[qslot*KMAX+pos] = d2;
                }
                cnt += nb;
            } else {
                unsigned rem = ball;
                while (rem) {
                    int l = __ffs(rem)-1; rem &= rem-1u;
                    float cd2 = __shfl_sync(0xffffffffu, d2, l);
                    int cj = base + l;
                    if (cnt < KMAX) {
                        if (lane==0){ s_pj[qslot*KMAX+cnt]=cj; s_pd[qslot*KMAX+cnt]=cd2; }
                        cnt++;
                    } else {
                        float e0 = s_pd[qslot*KMAX+lane],    e1 = s_pd[qslot*KMAX+32+lane];
                        int   j0 = s_pj[qslot*KMAX+lane],    j1 = s_pj[qslot*KMAX+32+lane];
                        float md; int ms, mj;
                        if (e1 > e0 || (e1==e0 && j1>j0)) { md=e1; ms=32+lane; mj=j1; }
                        else                               { md=e0; ms=lane;    mj=j0; }
                        #pragma unroll
                        for (int o=16;o;o>>=1){
                            float od = __shfl_xor_sync(~0u, md, o);
                            int   os = __shfl_xor_sync(~0u, ms, o);
                            int   oj = __shfl_xor_sync(~0u, mj, o);
                            if (od > md || (od==md && oj>mj)) { md=od; ms=os; mj=oj; }
                        }
                        if (cd2 < md) {
                            if (lane==0){ s_pj[qslot*KMAX+ms]=cj; s_pd[qslot*KMAX+ms]=cd2; }
                        }
                    }
                    __syncwarp();
                }
            }
        }
        if (lane==0) s_cnt[qslot] = cnt;
    }
    __syncthreads();

    if (tid==0){
        int acc=0;
        for (int i=0;i<QPB;i++){ s_qoff[i]=acc; acc+=s_cnt[i]; }
        s_qoff[QPB]=acc;
    }
    __syncthreads();
    for (int qq = 0; qq < 2; ++qq) {
        int qslot = w*2 + qq;
        int off = s_qoff[qslot], c = s_cnt[qslot];
        for (int e = lane; e < c; e += 32){ s_fi[off+e]=qslot; s_fj[off+e]=s_pj[qslot*KMAX+e]; }
    }
    for (int i = tid; i < QPB*COUT; i += 512) s_out[i] = 0u;
    __syncthreads();

    int total = s_qoff[QPB];
    int ty = tid >> 5, tx = tid & 31;

    for (int m0 = 0; m0 < total; m0 += MT) {
        for (int i = tid; i < MT*HDIM; i += 512) {
            int mp = i / HDIM, k = i % HDIM;
            float val = 0.f;
            if (m0 + mp < total) {
                int qi = s_fi[m0+mp], j = s_fj[m0+mp];
                val = fmaxf(P[(size_t)(b*MSRC + j)*HDIM + k] + Q[(size_t)(b*MSRC + q0 + qi)*HDIM + k], 0.f);
            }
            s_h[i] = val;
        }
        __syncthreads();

        for (int n0 = 0; n0 < COUT; n0 += NT) {
            float acc[4][4] = {};
            for (int k0 = 0; k0 < HDIM; k0 += KT) {
                for (int i = tid; i < KT*NT; i += 512) {
                    int kk = i / NT, nn = i % NT;
                    s_w[kk*(NT+4)+nn] = w2[(size_t)(k0+kk)*COUT + n0 + nn];
                }
                __syncthreads();
                #pragma unroll
                for (int kk = 0; kk < KT; ++kk) {
                    float a0 = s_h[(ty*4+0)*HDIM + k0+kk];
                    float a1 = s_h[(ty*4+1)*HDIM + k0+kk];
                    float a2 = s_h[(ty*4+2)*HDIM + k0+kk];
                    float a3 = s_h[(ty*4+3)*HDIM + k0+kk];
                    float4 bv = *(const float4*)&s_w[kk*(NT+4) + tx*4];
                    acc[0][0]+=a0*bv.x; acc[0][1]+=a0*bv.y; acc[0][2]+=a0*bv.z; acc[0][3]+=a0*bv.w;
                    acc[1][0]+=a1*bv.x; acc[1][1]+=a1*bv.y; acc[1][2]+=a1*bv.z; acc[1][3]+=a1*bv.w;
                    acc[2][0]+=a2*bv.x; acc[2][1]+=a2*bv.y; acc[2][2]+=a2*bv.z; acc[2][3]+=a2*bv.w;
                    acc[3][0]+=a3*bv.x; acc[3][1]+=a3*bv.y; acc[3][2]+=a3*bv.z; acc[3][3]+=a3*bv.w;
                }
                __syncthreads();
            }
            #pragma unroll
            for (int mi=0; mi<4; ++mi) {
                int mp = ty*4 + mi;
                if (m0 + mp < total) {
                    int qi = s_fi[m0+mp];
                    #pragma unroll
                    for (int ni=0; ni<4; ++ni) {
                        int n = n0 + tx*4 + ni;
                        float val = fmaxf(acc[mi][ni] + b2[n], 0.f);
                        atomicMax(&s_out[qi*COUT + n], __float_as_uint(val));
                    }
                }
            }
            __syncthreads();
        }
    }

    for (int i = tid; i < QPB*COUT; i += 512) {
        int q = i / COUT, c = i % COUT;
        out[(size_t)(b*MSRC + q0 + q)*COUT + c] = __uint_as_float(s_out[i]);
    }
}

// ---------------- fused conv1 + fps2 + batch2 (single-kernel overlap) ----------------
__global__ void __launch_bounds__(512)
k_conv1_fps2(const float* __restrict__ w2, const float* __restrict__ b2,
             float* __restrict__ batch_out, float R2) {
    extern __shared__ char smemraw[];
    if (blockIdx.x < CONV1_BLOCKS) {
        conv_body<M1,H1,C1OUT>(smemraw, blockIdx.x, g_pos1, g_P1, g_Q1, w2, b2, g_x1, R2);
    } else {
        int b = blockIdx.x - CONV1_BLOCKS;       // 0..7
        fps_body<M1, M2, 2>(smemraw, b, g_pos1, g_idx2, g_pos2);
        if (batch_out) {                          // 8 blocks x 512 threads = 4096 = B_*M2
            batch_out[b*512 + threadIdx.x] = (float)b;
        }
    }
}

// ---------------- standalone conv2 ----------------
__global__ void __launch_bounds__(512)
k_conv2(const float* __restrict__ w2, const float* __restrict__ b2,
        float* __restrict__ out, float R2) {
    extern __shared__ char smemraw[];
    conv_body<M2,H2,C2OUT>(smemraw, blockIdx.x, g_pos2, g_P2, g_Q2, w2, b2, out, R2);
}

// ---------------- launch ----------------
extern "C" void kernel_launch(void* const* d_in, const int* in_sizes, int n_in,
                              void* d_out, int out_size) {
    const float *pos, *c1_w1, *c1_b1, *c1_g, *c1_be, *c1_m, *c1_v, *c1_w2, *c1_b2;
    const float *c2_w1, *c2_b1, *c2_g, *c2_be, *c2_m, *c2_v, *c2_w2, *c2_b2;
    if (in_sizes[0] == B_*N_*3) {
        pos   = (const float*)d_in[0];
        c1_w1 = (const float*)d_in[1];  c1_b1 = (const float*)d_in[2];
        c1_g  = (const float*)d_in[3];  c1_be = (const float*)d_in[4];
        c1_m  = (const float*)d_in[5];  c1_v  = (const float*)d_in[6];
        c1_w2 = (const float*)d_in[7];  c1_b2 = (const float*)d_in[8];
        c2_w1 = (const float*)d_in[9];  c2_b1 = (const float*)d_in[10];
        c2_g  = (const float*)d_in[11]; c2_be = (const float*)d_in[12];
        c2_m  = (const float*)d_in[13]; c2_v  = (const float*)d_in[14];
        c2_w2 = (const float*)d_in[15]; c2_b2 = (const float*)d_in[16];
    } else {
        c1_b1 = (const float*)d_in[1];  c1_b2 = (const float*)d_in[2];
        c1_be = (const float*)d_in[3];  c1_g  = (const float*)d_in[4];
        c1_m  = (const float*)d_in[5];  c1_v  = (const float*)d_in[6];
        c1_w1 = (const float*)d_in[7];  c1_w2 = (const float*)d_in[8];
        c2_b1 = (const float*)d_in[9];  c2_b2 = (const float*)d_in[10];
        c2_be = (const float*)d_in[11]; c2_g  = (const float*)d_in[12];
        c2_m  = (const float*)d_in[13]; c2_v  = (const float*)d_in[14];
        c2_w1 = (const float*)d_in[15]; c2_w2 = (const float*)d_in[16];
        pos   = (const float*)d_in[17];
    }
    float* out = (float*)d_out;

    const size_t smem1 = conv_smem_bytes(M1, H1, C1OUT);
    const size_t smem2 = conv_smem_bytes(M2, H2, C2OUT);
    const size_t smemP2 = (64*128 + 128*68) * sizeof(float);
    cudaFuncSetAttribute(k_conv1_fps2, cudaFuncAttributeMaxDynamicSharedMemorySize, (int)smem1);
    cudaFuncSetAttribute(k_conv2,      cudaFuncAttributeMaxDynamicSharedMemorySize, (int)smem2);
    cudaFuncSetAttribute(k_prep2,      cudaFuncAttributeMaxDynamicSharedMemorySize, (int)smemP2);

    float* batch_out = ((size_t)out_size >= (size_t)B_*M2*C2OUT + B_*M2)
                     ? out + (size_t)B_*M2*C2OUT : nullptr;

    k_norm_fps1<<<B_, 512>>>(pos);
    k_prep1<<<(B_*M1*H1 + 255)/256, 256>>>(c1_w1, c1_b1, c1_g, c1_be, c1_m, c1_v);
    {
        float r2 = (float)(0.1 * 0.1);   // matches JAX f32 scalar exactly
        k_conv1_fps2<<<CONV1_BLOCKS + B_, 512, smem1>>>(c1_w2, c1_b2, batch_out, r2);
    }
    k_prep2<<<dim3(B_*M2/64, H2/64), 256, smemP2>>>(c2_w1, c2_b1, c2_g, c2_be, c2_m, c2_v);
    {
        float r2 = (float)(0.25 * 0.25);
        k_conv2<<<B_*(M2/QPB), 512, smem2>>>(c2_w2, c2_b2, out, r2);
    }
    (void)in_sizes; (void)n_in;
}

// round 17
// speedup vs baseline: 2.1894x; 1.0166x over previous
#include <cuda_runtime.h>
#include <cuda_bf16.h>
#include <math.h>

// Problem constants
constexpr int B_ = 8, N_ = 2048;
constexpr int M1 = 1024, M2 = 512;
constexpr int H1 = 128, C1OUT = 128;
constexpr int H2 = 256, C2OUT = 512;
constexpr int KMAX = 64;
constexpr int QPB = 32;   // queries per conv block (2 per warp)
constexpr int MT  = 64;   // pair m-tile
constexpr int NT  = 128;  // n-tile
constexpr int KT  = 32;   // k-tile
constexpr int CONV1_BLOCKS = B_*(M1/QPB);   // 256

// ---------------- scratch (__device__ globals; device-code references ONLY) ----------------
__device__ int   g_idx1[B_*M1];
__device__ float g_pos1[B_*M1*3];
__device__ float g_P1  [B_*M1*H1];
__device__ float g_Q1  [B_*M1*H1];
__device__ float g_x1  [B_*M1*C1OUT];
__device__ int   g_idx2[B_*M2];
__device__ float g_pos2[B_*M2*3];
__device__ float g_P2  [B_*M2*H2];
__device__ float g_Q2  [B_*M2*H2];

// ---------------- packed f32x2 helpers (bit-exact per-lane .rn) ----------------
__device__ __forceinline__ unsigned long long pk2(float a, float b){
    unsigned long long r;
    asm("mov.b64 %0, {%1, %2};" : "=l"(r) : "f"(a), "f"(b));
    return r;
}
__device__ __forceinline__ void upk2(unsigned long long v, float& a, float& b){
    asm("mov.b64 {%0, %1}, %2;" : "=f"(a), "=f"(b) : "l"(v));
}
__device__ __forceinline__ unsigned long long add2(unsigned long long a, unsigned long long b){
    unsigned long long r;
    asm("add.rn.f32x2 %0, %1, %2;" : "=l"(r) : "l"(a), "l"(b));
    return r;
}
__device__ __forceinline__ unsigned long long mul2(unsigned long long a, unsigned long long b){
    unsigned long long r;
    asm("mul.rn.f32x2 %0, %1, %2;" : "=l"(r) : "l"(a), "l"(b));
    return r;
}

// ---------------- FPS core (shared by both levels) ----------------
// Smem layout (carved from dynamic): nsx2/nsy2/nsz2 [NP] ull  (pk2(-c,-c) per point),
// wb[2][32] unsigned, wi[2][32] int, s_hist[KSEL] int.
// Per-point registers hold packed pairs of (normalized) coordinates.
template<int NP, int KSEL, int PT, bool NORM>
__device__ __forceinline__ void fps_core(char* smemraw, int b,
                                         const float* __restrict__ src,
                                         int* __restrict__ idx_out,
                                         float* __restrict__ pos_out) {
    constexpr int T = 512;
    unsigned long long* nsx2 = (unsigned long long*)smemraw;
    unsigned long long* nsy2 = nsx2 + NP;
    unsigned long long* nsz2 = nsy2 + NP;
    unsigned* wb = (unsigned*)(nsz2 + NP);     // [2][32]
    int*      wi = (int*)(wb + 64);            // [2][32]
    int*  s_hist = wi + 64;                    // [KSEL]

    int t = threadIdx.x, lane = t & 31, w = t >> 5;
    const float* p = src + b*NP*3;

    float mx=0.f, my=0.f, mz=0.f, dx0=1.f, dy0=1.f, dz0=1.f;
    if (NORM) {
        __shared__ float s_mean[3], s_den[3];
        if (t < 3) {
            float s = 0.f;
            for (int i = 0; i < NP; ++i) s = __fadd_rn(s, p[i*3 + t]);
            s_mean[t] = __fdiv_rn(s, (float)NP);
        }
        __syncthreads();
        if (t < 3) {
            float mu = s_mean[t];
            float s = 0.f;
            for (int i = 0; i < NP; ++i) {
                float d = __fsub_rn(p[i*3 + t], mu);
                s = __fadd_rn(s, __fmul_rn(d, d));
            }
            float var = __fdiv_rn(s, (float)(NP - 1));
            s_den[t] = __fadd_rn(__fsqrt_rn(var), 1e-6f);
        }
        __syncthreads();
        mx = s_mean[0]; my = s_mean[1]; mz = s_mean[2];
        dx0 = s_den[0]; dy0 = s_den[1]; dz0 = s_den[2];
    }

    unsigned long long px2[PT/2], py2[PT/2], pz2[PT/2];
    float dd[PT];
    {
        float xs_[PT], ys_[PT], zs_[PT];
        #pragma unroll
        for (int s=0;s<PT;s++){
            int i = t + s*T;
            float x = p[i*3+0], y = p[i*3+1], z = p[i*3+2];
            if (NORM) {
                x = __fdiv_rn(__fsub_rn(x, mx), dx0);
                y = __fdiv_rn(__fsub_rn(y, my), dy0);
                z = __fdiv_rn(__fsub_rn(z, mz), dz0);
            }
            xs_[s]=x; ys_[s]=y; zs_[s]=z; dd[s]=1e10f;
            nsx2[i] = pk2(-x,-x);
            nsy2[i] = pk2(-y,-y);
            nsz2[i] = pk2(-z,-z);
        }
        #pragma unroll
        for (int q=0;q<PT/2;q++){
            px2[q]=pk2(xs_[2*q],xs_[2*q+1]);
            py2[q]=pk2(ys_[2*q],ys_[2*q+1]);
            pz2[q]=pk2(zs_[2*q],zs_[2*q+1]);
        }
    }
    if (t < 32) { wb[t]=0u; wb[32+t]=0u; wi[t]=0x7fffffff; wi[32+t]=0x7fffffff; }
    if (t==0) s_hist[0] = 0;
    __syncthreads();

    int win = 0;
    for (int it=1; it<KSEL; ++it) {
        // pre-negated packed query coords: one LDS.64 broadcast per axis
        unsigned long long nlx2 = nsx2[win];
        unsigned long long nly2 = nsy2[win];
        unsigned long long nlz2 = nsz2[win];
        float bd = -1.f;
        #pragma unroll
        for (int q=0;q<PT/2;q++){
            unsigned long long dx = add2(px2[q], nlx2);
            unsigned long long dy = add2(py2[q], nly2);
            unsigned long long dz = add2(pz2[q], nlz2);
            unsigned long long d2 = add2(add2(mul2(dx,dx), mul2(dy,dy)), mul2(dz,dz));
            float d0, d1; upk2(d2, d0, d1);
            dd[2*q]   = fminf(dd[2*q],   d0);  bd = fmaxf(bd, dd[2*q]);
            dd[2*q+1] = fminf(dd[2*q+1], d1);  bd = fmaxf(bd, dd[2*q+1]);
        }
        // resolve argmax once: lowest s with dd[s]==bd (descending scan)
        int bi = t + (PT-1)*T;
        #pragma unroll
        for (int s=PT-2;s>=0;--s) if (dd[s] == bd) bi = t + s*T;
        unsigned mybits = __float_as_uint(bd);
        unsigned mb = __reduce_max_sync(0xffffffffu, mybits);
        unsigned cand = (mybits == mb) ? (unsigned)bi : 0xffffffffu;
        unsigned mi = __reduce_min_sync(0xffffffffu, cand);
        int par = it & 1;
        if (lane==0){ wb[par*32+w]=mb; wi[par*32+w]=(int)mi; }
        __syncthreads();                                    // ONLY barrier per iteration
        // lanes 16-31 hold init values (0 / 0x7fffffff) forever -> safe unpredicated
        unsigned vb = wb[par*32+lane];
        int      vi = wi[par*32+lane];
        unsigned mb2 = __reduce_max_sync(0xffffffffu, vb);
        unsigned cand2 = (vb==mb2) ? (unsigned)vi : 0xffffffffu;
        win = (int)__reduce_min_sync(0xffffffffu, cand2);
        if (t==0) s_hist[it] = win;
    }
    __syncthreads();
    // bulk write-out, off the serial critical path (coords = -packed_hi)
    for (int i = t; i < KSEL; i += T) {
        int h = s_hist[i];
        idx_out[b*KSEL+i] = h;
        float xv, yv, zv, dmy;
        upk2(nsx2[h], xv, dmy);
        upk2(nsy2[h], yv, dmy);
        upk2(nsz2[h], zv, dmy);
        pos_out[(b*KSEL+i)*3+0] = -xv;
        pos_out[(b*KSEL+i)*3+1] = -yv;
        pos_out[(b*KSEL+i)*3+2] = -zv;
    }
}

// ---------------- fused normalize + FPS level 1 (dynamic smem) ----------------
__global__ void __launch_bounds__(512)
k_norm_fps1(const float* __restrict__ pos) {
    extern __shared__ char smemraw[];
    fps_core<N_, M1, 4, true>(smemraw, blockIdx.x, pos, g_idx1, g_pos1);
}

constexpr size_t fps1_smem_bytes() {
    return (size_t)(3*N_*8 + 64*4 + 64*4 + M1*4);
}
constexpr size_t fps2_smem_bytes() {
    return (size_t)(3*M1*8 + 64*4 + 64*4 + M2*4);
}

// ---------------- level-1 P/Q precompute (BN folded) ----------------
__global__ void k_prep1(const float* __restrict__ w1, const float* __restrict__ b1,
                        const float* __restrict__ g, const float* __restrict__ beta,
                        const float* __restrict__ m, const float* __restrict__ v) {
    int idx = blockIdx.x*256 + threadIdx.x;
    if (idx >= B_*M1*H1) return;
    int c = idx & (H1-1), pj = idx >> 7;
    float x = g_pos1[pj*3+0], y = g_pos1[pj*3+1], z = g_pos1[pj*3+2];
    float s = g[c] / sqrtf(v[c] + 1e-5f);
    float t = beta[c] - m[c]*s;
    float wa0=w1[0*H1+c], wa1=w1[1*H1+c], wa2=w1[2*H1+c];
    float wb0=w1[3*H1+c], wb1=w1[4*H1+c], wb2=w1[5*H1+c];
    float A = x*(wa0+wb0) + y*(wa1+wb1) + z*(wa2+wb2) + b1[c];
    g_P1[idx] = A * s;
    float q = -(x*wb0 + y*wb1 + z*wb2);
    g_Q1[idx] = q * s + t;
}

// ---------------- level-2 P AND Q precompute (fused): gathered GEMM + affine ----------------
__global__ void k_prep2(const float* __restrict__ w1, const float* __restrict__ b1,
                        const float* __restrict__ g, const float* __restrict__ beta,
                        const float* __restrict__ m, const float* __restrict__ v) {
    extern __shared__ char smemraw[];
    float* xs = (float*)smemraw;            // [64][128]
    float* ws = xs + 64*128;                // [128][68] padded
    int tid = threadIdx.x;                  // 256
    int row0 = blockIdx.x * 64;
    int n0   = blockIdx.y * 64;
    int b = row0 / M2;

    for (int i = tid; i < 64*128; i += 256) {
        int r = i >> 7, k = i & 127;
        int jj = g_idx2[row0 + r];
        xs[r*128 + k] = g_x1[(b*M1 + jj)*H1 + k];
    }
    for (int i = tid; i < 128*64; i += 256) {
        int k = i >> 6, nn = i & 63;
        ws[k*68 + nn] = w1[k*H2 + n0 + nn];
    }
    __syncthreads();

    int ty = tid >> 4, tx = tid & 15;
    float acc[4][4] = {};
    #pragma unroll 4
    for (int k = 0; k < 128; ++k) {
        float a0 = xs[(ty*4+0)*128 + k];
        float a1 = xs[(ty*4+1)*128 + k];
        float a2 = xs[(ty*4+2)*128 + k];
        float a3 = xs[(ty*4+3)*128 + k];
        float4 bv = *(const float4*)&ws[k*68 + tx*4];
        acc[0][0]+=a0*bv.x; acc[0][1]+=a0*bv.y; acc[0][2]+=a0*bv.z; acc[0][3]+=a0*bv.w;
        acc[1][0]+=a1*bv.x; acc[1][1]+=a1*bv.y; acc[1][2]+=a1*bv.z; acc[1][3]+=a1*bv.w;
        acc[2][0]+=a2*bv.x; acc[2][1]+=a2*bv.y; acc[2][2]+=a2*bv.z; acc[2][3]+=a2*bv.w;
        acc[3][0]+=a3*bv.x; acc[3][1]+=a3*bv.y; acc[3][2]+=a3*bv.z; acc[3][3]+=a3*bv.w;
    }
    #pragma unroll
    for (int mi=0; mi<4; ++mi) {
        int r = row0 + ty*4 + mi;
        float px = g_pos2[r*3+0], py = g_pos2[r*3+1], pz = g_pos2[r*3+2];
        #pragma unroll
        for (int ni=0; ni<4; ++ni) {
            int n = n0 + tx*4 + ni;
            float s = g[n] / sqrtf(v[n] + 1e-5f);
            float wpx = w1[128*H2 + n], wpy = w1[129*H2 + n], wpz = w1[130*H2 + n];
            float dot = px*wpx + py*wpy + pz*wpz;
            g_P2[r*H2 + n] = (acc[mi][ni] + dot + b1[n]) * s;
            g_Q2[r*H2 + n] = -dot * s + (beta[n] - m[n]*s);
        }
    }
}

// ---------------- ball-query + pair-list GEMM + max aggregation (device body) ----------------
constexpr size_t conv_smem_bytes(int MSRC, int HDIM, int COUT) {
    return (size_t)(MSRC*3 + QPB*KMAX + QPB*KMAX + QPB + QPB*KMAX + QPB*KMAX + 64
                    + MT*HDIM + KT*(NT+4) + QPB*COUT) * 4;
}

template<int MSRC, int HDIM, int COUT>
__device__ __forceinline__ void conv_body(char* smemraw, int blk,
        const float* __restrict__ srcpos, const float* __restrict__ P,
        const float* __restrict__ Q, const float* __restrict__ w2,
        const float* __restrict__ b2, float* __restrict__ out, float R2) {
    float*    s_pos = (float*)smemraw;                 // MSRC*3
    float*    s_pd  = s_pos + MSRC*3;                  // QPB*KMAX
    int*      s_pj  = (int*)(s_pd + QPB*KMAX);         // QPB*KMAX
    int*      s_cnt = s_pj + QPB*KMAX;                 // QPB
    int*      s_fi  = s_cnt + QPB;                     // QPB*KMAX
    int*      s_fj  = s_fi + QPB*KMAX;                 // QPB*KMAX
    int*      s_qoff= s_fj + QPB*KMAX;                 // 64
    float*    s_h   = (float*)(s_qoff + 64);           // MT*HDIM
    float*    s_w   = s_h + MT*HDIM;                   // KT*(NT+4)
    unsigned* s_out = (unsigned*)(s_w + KT*(NT+4));    // QPB*COUT

    int b  = blk / (MSRC/QPB);
    int q0 = (blk % (MSRC/QPB)) * QPB;
    int tid = threadIdx.x, lane = tid & 31, w = tid >> 5;

    for (int i = tid; i < MSRC*3; i += 512) s_pos[i] = srcpos[b*MSRC*3 + i];
    __syncthreads();

    for (int qq = 0; qq < 2; ++qq) {
        int qslot = w*2 + qq;
        int qi = q0 + qslot;
        float qx = s_pos[qi*3+0], qy = s_pos[qi*3+1], qz = s_pos[qi*3+2];
        int cnt = 0;
        for (int base = 0; base < MSRC; base += 32) {
            int j = base + lane;
            float dx = __fsub_rn(s_pos[j*3+0], qx);
            float dy = __fsub_rn(s_pos[j*3+1], qy);
            float dz = __fsub_rn(s_pos[j*3+2], qz);
            float d2 = __fadd_rn(__fadd_rn(__fmul_rn(dx,dx),__fmul_rn(dy,dy)),__fmul_rn(dz,dz));
            bool pred = (d2 <= R2);
            unsigned ball = __ballot_sync(0xffffffffu, pred);
            int nb = __popc(ball);
            if (cnt + nb <= KMAX) {
                if (pred) {
                    int pos = cnt + __popc(ball & ((1u<<lane)-1u));
                    s_pj[qslot*KMAX+pos] = j; s_pd[qslot*KMAX+pos] = d2;
                }
                cnt += nb;
            } else {
                unsigned rem = ball;
                while (rem) {
                    int l = __ffs(rem)-1; rem &= rem-1u;
                    float cd2 = __shfl_sync(0xffffffffu, d2, l);
                    int cj = base + l;
                    if (cnt < KMAX) {
                        if (lane==0){ s_pj[qslot*KMAX+cnt]=cj; s_pd[qslot*KMAX+cnt]=cd2; }
                        cnt++;
                    } else {
                        float e0 = s_pd[qslot*KMAX+lane],    e1 = s_pd[qslot*KMAX+32+lane];
                        int   j0 = s_pj[qslot*KMAX+lane],    j1 = s_pj[qslot*KMAX+32+lane];
                        float md; int ms, mj;
                        if (e1 > e0 || (e1==e0 && j1>j0)) { md=e1; ms=32+lane; mj=j1; }
                        else                               { md=e0; ms=lane;    mj=j0; }
                        #pragma unroll
                        for (int o=16;o;o>>=1){
                            float od = __shfl_xor_sync(~0u, md, o);
                            int   os = __shfl_xor_sync(~0u, ms, o);
                            int   oj = __shfl_xor_sync(~0u, mj, o);
                            if (od > md || (od==md && oj>mj)) { md=od; ms=os; mj=oj; }
                        }
                        if (cd2 < md) {
                            if (lane==0){ s_pj[qslot*KMAX+ms]=cj; s_pd[qslot*KMAX+ms]=cd2; }
                        }
                    }
                    __syncwarp();
                }
            }
        }
        if (lane==0) s_cnt[qslot] = cnt;
    }
    __syncthreads();

    if (tid==0){
        int acc=0;
        for (int i=0;i<QPB;i++){ s_qoff[i]=acc; acc+=s_cnt[i]; }
        s_qoff[QPB]=acc;
    }
    __syncthreads();
    for (int qq = 0; qq < 2; ++qq) {
        int qslot = w*2 + qq;
        int off = s_qoff[qslot], c = s_cnt[qslot];
        for (int e = lane; e < c; e += 32){ s_fi[off+e]=qslot; s_fj[off+e]=s_pj[qslot*KMAX+e]; }
    }
    for (int i = tid; i < QPB*COUT; i += 512) s_out[i] = 0u;
    __syncthreads();

    int total = s_qoff[QPB];
    int ty = tid >> 5, tx = tid & 31;

    for (int m0 = 0; m0 < total; m0 += MT) {
        for (int i = tid; i < MT*HDIM; i += 512) {
            int mp = i / HDIM, k = i % HDIM;
            float val = 0.f;
            if (m0 + mp < total) {
                int qi = s_fi[m0+mp], j = s_fj[m0+mp];
                val = fmaxf(P[(size_t)(b*MSRC + j)*HDIM + k] + Q[(size_t)(b*MSRC + q0 + qi)*HDIM + k], 0.f);
            }
            s_h[i] = val;
        }
        __syncthreads();

        for (int n0 = 0; n0 < COUT; n0 += NT) {
            float acc[4][4] = {};
            for (int k0 = 0; k0 < HDIM; k0 += KT) {
                for (int i = tid; i < KT*NT; i += 512) {
                    int kk = i / NT, nn = i % NT;
                    s_w[kk*(NT+4)+nn] = w2[(size_t)(k0+kk)*COUT + n0 + nn];
                }
                __syncthreads();
                #pragma unroll
                for (int kk = 0; kk < KT; ++kk) {
                    float a0 = s_h[(ty*4+0)*HDIM + k0+kk];
                    float a1 = s_h[(ty*4+1)*HDIM + k0+kk];
                    float a2 = s_h[(ty*4+2)*HDIM + k0+kk];
                    float a3 = s_h[(ty*4+3)*HDIM + k0+kk];
                    float4 bv = *(const float4*)&s_w[kk*(NT+4) + tx*4];
                    acc[0][0]+=a0*bv.x; acc[0][1]+=a0*bv.y; acc[0][2]+=a0*bv.z; acc[0][3]+=a0*bv.w;
                    acc[1][0]+=a1*bv.x; acc[1][1]+=a1*bv.y; acc[1][2]+=a1*bv.z; acc[1][3]+=a1*bv.w;
                    acc[2][0]+=a2*bv.x; acc[2][1]+=a2*bv.y; acc[2][2]+=a2*bv.z; acc[2][3]+=a2*bv.w;
                    acc[3][0]+=a3*bv.x; acc[3][1]+=a3*bv.y; acc[3][2]+=a3*bv.z; acc[3][3]+=a3*bv.w;
                }
                __syncthreads();
            }
            #pragma unroll
            for (int mi=0; mi<4; ++mi) {
                int mp = ty*4 + mi;
                if (m0 + mp < total) {
                    int qi = s_fi[m0+mp];
                    #pragma unroll
                    for (int ni=0; ni<4; ++ni) {
                        int n = n0 + tx*4 + ni;
                        float val = fmaxf(acc[mi][ni] + b2[n], 0.f);
                        atomicMax(&s_out[qi*COUT + n], __float_as_uint(val));
                    }
                }
            }
            __syncthreads();
        }
    }

    for (int i = tid; i < QPB*COUT; i += 512) {
        int q = i / COUT, c = i % COUT;
        out[(size_t)(b*MSRC + q0 + q)*COUT + c] = __uint_as_float(s_out[i]);
    }
}

// ---------------- fused conv1 + fps2 + batch2 (single-kernel overlap) ----------------
__global__ void __launch_bounds__(512)
k_conv1_fps2(const float* __restrict__ w2, const float* __restrict__ b2,
             float* __restrict__ batch_out, float R2) {
    extern __shared__ char smemraw[];
    if (blockIdx.x < CONV1_BLOCKS) {
        conv_body<M1,H1,C1OUT>(smemraw, blockIdx.x, g_pos1, g_P1, g_Q1, w2, b2, g_x1, R2);
    } else {
        int b = blockIdx.x - CONV1_BLOCKS;       // 0..7
        fps_core<M1, M2, 2, false>(smemraw, b, g_pos1, g_idx2, g_pos2);
        if (batch_out) {                          // 8 blocks x 512 threads = 4096 = B_*M2
            batch_out[b*512 + threadIdx.x] = (float)b;
        }
    }
}

// ---------------- standalone conv2 ----------------
__global__ void __launch_bounds__(512)
k_conv2(const float* __restrict__ w2, const float* __restrict__ b2,
        float* __restrict__ out, float R2) {
    extern __shared__ char smemraw[];
    conv_body<M2,H2,C2OUT>(smemraw, blockIdx.x, g_pos2, g_P2, g_Q2, w2, b2, out, R2);
}

// ---------------- launch ----------------
extern "C" void kernel_launch(void* const* d_in, const int* in_sizes, int n_in,
                              void* d_out, int out_size) {
    const float *pos, *c1_w1, *c1_b1, *c1_g, *c1_be, *c1_m, *c1_v, *c1_w2, *c1_b2;
    const float *c2_w1, *c2_b1, *c2_g, *c2_be, *c2_m, *c2_v, *c2_w2, *c2_b2;
    if (in_sizes[0] == B_*N_*3) {
        pos   = (const float*)d_in[0];
        c1_w1 = (const float*)d_in[1];  c1_b1 = (const float*)d_in[2];
        c1_g  = (const float*)d_in[3];  c1_be = (const float*)d_in[4];
        c1_m  = (const float*)d_in[5];  c1_v  = (const float*)d_in[6];
        c1_w2 = (const float*)d_in[7];  c1_b2 = (const float*)d_in[8];
        c2_w1 = (const float*)d_in[9];  c2_b1 = (const float*)d_in[10];
        c2_g  = (const float*)d_in[11]; c2_be = (const float*)d_in[12];
        c2_m  = (const float*)d_in[13]; c2_v  = (const float*)d_in[14];
        c2_w2 = (const float*)d_in[15]; c2_b2 = (const float*)d_in[16];
    } else {
        c1_b1 = (const float*)d_in[1];  c1_b2 = (const float*)d_in[2];
        c1_be = (const float*)d_in[3];  c1_g  = (const float*)d_in[4];
        c1_m  = (const float*)d_in[5];  c1_v  = (const float*)d_in[6];
        c1_w1 = (const float*)d_in[7];  c1_w2 = (const float*)d_in[8];
        c2_b1 = (const float*)d_in[9];  c2_b2 = (const float*)d_in[10];
        c2_be = (const float*)d_in[11]; c2_g  = (const float*)d_in[12];
        c2_m  = (const float*)d_in[13]; c2_v  = (const float*)d_in[14];
        c2_w1 = (const float*)d_in[15]; c2_w2 = (const float*)d_in[16];
        pos   = (const float*)d_in[17];
    }
    float* out = (float*)d_out;

    const size_t smemF1 = fps1_smem_bytes();
    const size_t smem1a = conv_smem_bytes(M1, H1, C1OUT);
    const size_t smem1b = fps2_smem_bytes();
    const size_t smem1  = (smem1a > smem1b) ? smem1a : smem1b;
    const size_t smem2  = conv_smem_bytes(M2, H2, C2OUT);
    const size_t smemP2 = (64*128 + 128*68) * sizeof(float);
    cudaFuncSetAttribute(k_norm_fps1,  cudaFuncAttributeMaxDynamicSharedMemorySize, (int)smemF1);
    cudaFuncSetAttribute(k_conv1_fps2, cudaFuncAttributeMaxDynamicSharedMemorySize, (int)smem1);
    cudaFuncSetAttribute(k_conv2,      cudaFuncAttributeMaxDynamicSharedMemorySize, (int)smem2);
    cudaFuncSetAttribute(k_prep2,      cudaFuncAttributeMaxDynamicSharedMemorySize, (int)smemP2);

    float* batch_out = ((size_t)out_size >= (size_t)B_*M2*C2OUT + B_*M2)
                     ? out + (size_t)B_*M2*C2OUT : nullptr;

    k_norm_fps1<<<B_, 512, smemF1>>>(pos);
    k_prep1<<<(B_*M1*H1 + 255)/256, 256>>>(c1_w1, c1_b1, c1_g, c1_be, c1_m, c1_v);
    {
        float r2 = (float)(0.1 * 0.1);   // matches JAX f32 scalar exactly
        k_conv1_fps2<<<CONV1_BLOCKS + B_, 512, smem1>>>(c1_w2, c1_b2, batch_out, r2);
    }
    k_prep2<<<dim3(B_*M2/64, H2/64), 256, smemP2>>>(c2_w1, c2_b1, c2_g, c2_be, c2_m, c2_v);
    {
        float r2 = (float)(0.25 * 0.25);
        k_conv2<<<B_*(M2/QPB), 512, smem2>>>(c2_w2, c2_b2, out, r2);
    }
    (void)in_sizes; (void)n_in;
}